// round 3
// baseline (speedup 1.0000x reference)
#include <cuda_runtime.h>

#define Bb 8
#define Cc 128
#define Hh 128
#define Ww 128
#define HW 16384
#define NELEM (Bb*Cc*HW)
#define DD 2048
#define BH 64

// ---------------- scratch ----------------------------------------------------
__device__ float g_x1[NELEM];     // dw output (att); later out3
__device__ float g_y[NELEM];      // y1; later out4
__device__ float g_s[NELEM];      // out1
__device__ float g_out2[NELEM];   // out2; later merged o3+o4
__device__ float g_hwc1[NELEM];   // y2 first, then hwc(out1)
__device__ float g_whc1[NELEM];   // y3 first, then whc(out1)
__device__ float g_whc2[NELEM];
__device__ float g_A1[BH*Hh*Ww];
__device__ float g_A2[BH*Hh*Ww];
__device__ float g_n_hwc1[BH*Hh];
__device__ float g_n_whc1[BH*Ww];
__device__ float g_n_whc2[BH*Ww];
__device__ float g_stats[6*Cc];
__device__ float g_mu[Bb*HW];
__device__ float g_rs[Bb*HW];
__device__ float g_wp1[Cc*Cc];
__device__ float g_wp2[9*Cc*Cc];
__device__ float g_wp3[9*Cc*Cc];
__device__ float g_wpo1[Cc*Cc];
__device__ float g_wpo2[Cc*Cc];

// ---------------- tf32 helpers ----------------------------------------------
__device__ __forceinline__ unsigned cvt1(float f) {
    unsigned u; asm("cvt.rna.tf32.f32 %0, %1;" : "=r"(u) : "f"(f)); return u;
}
__device__ __forceinline__ uint4 cvt4(float4 f) {
    uint4 u;
    asm("cvt.rna.tf32.f32 %0, %1;" : "=r"(u.x) : "f"(f.x));
    asm("cvt.rna.tf32.f32 %0, %1;" : "=r"(u.y) : "f"(f.y));
    asm("cvt.rna.tf32.f32 %0, %1;" : "=r"(u.z) : "f"(f.z));
    asm("cvt.rna.tf32.f32 %0, %1;" : "=r"(u.w) : "f"(f.w));
    return u;
}
__device__ __forceinline__ void mma_tf32(float* c, unsigned a0, unsigned a1,
                                         unsigned a2, unsigned a3,
                                         unsigned b0, unsigned b1) {
    asm volatile("mma.sync.aligned.m16n8k8.row.col.f32.tf32.tf32.f32 "
                 "{%0,%1,%2,%3}, {%4,%5,%6,%7}, {%8,%9}, {%0,%1,%2,%3};"
                 : "+f"(c[0]), "+f"(c[1]), "+f"(c[2]), "+f"(c[3])
                 : "r"(a0), "r"(a1), "r"(a2), "r"(a3), "r"(b0), "r"(b1));
}

// ---------------- weight pack ------------------------------------------------
__global__ void pack_w(const float* __restrict__ w, float* __restrict__ wp, int taps) {
    int idx = blockIdx.x * 256 + threadIdx.x;
    int total = Cc * Cc * taps;
    if (idx < total) {
        int co = idx / (Cc * taps);
        int rem = idx % (Cc * taps);
        int ci = rem / taps;
        int tap = rem % taps;
        wp[(tap * Cc + ci) * Cc + co] = __uint_as_float(cvt1(w[idx]));
    }
}

// ---------------- LN pixel stats only ---------------------------------------
__global__ __launch_bounds__(128) void ln_stats(const float* __restrict__ x,
                                                float* __restrict__ mu,
                                                float* __restrict__ rs) {
    int bi = blockIdx.x;
    int b = bi >> 7, i = bi & 127;
    int w = threadIdx.x;
    const float* p = x + (size_t)b * Cc * HW + i * Ww + w;
    float s = 0.f, sq = 0.f;
    for (int c = 0; c < Cc; c++) { float v = p[(size_t)c * HW]; s += v; sq += v * v; }
    float m = s * (1.f / Cc);
    float var = sq * (1.f / Cc) - m * m;
    mu[b * HW + i * Ww + w] = m;
    rs[b * HW + i * Ww + w] = rsqrtf(var + 1e-5f);
}

// ---------------- conv as implicit-im2col tf32 GEMM --------------------------
__global__ __launch_bounds__(256) void conv_tf32(const float* __restrict__ in,
                                                 const float* __restrict__ wp,
                                                 const float* __restrict__ resid,
                                                 float* __restrict__ out,
                                                 int taps, int dil) {
    __shared__ unsigned As[32][136];
    __shared__ unsigned Bs[32][136];
    int bi = blockIdx.x;
    int b = bi >> 7, i = bi & 127;
    int tid = threadIdx.x, lane = tid & 31, wid = tid >> 5;
    int gid = lane >> 2, tig = lane & 3;
    int m_base = (wid >> 2) * 64, n_base = (wid & 3) * 32;
    float C[4][4][4];
#pragma unroll
    for (int a = 0; a < 4; a++)
#pragma unroll
        for (int c = 0; c < 4; c++)
#pragma unroll
            for (int d = 0; d < 4; d++) C[a][c][d] = 0.f;
    int K = taps * 128, nch = K >> 5;
    const float* inb = in + (size_t)b * Cc * HW;
    uint4 ra[4];
    float rb[16];
#pragma unroll
    for (int r = 0; r < 4; r++) {
        int e = (tid + r * 256) * 4;
        int kk = e >> 7, co = e & 127;
        ra[r] = *(const uint4*)&wp[(size_t)kk * 128 + co];
    }
#pragma unroll
    for (int r = 0; r < 16; r++) {
        int e = tid + r * 256;
        int kk = e >> 7, w = e & 127;
        int tap = kk >> 7, ci = kk & 127;
        int dy = 0, dx = 0;
        if (taps == 9) { dy = (tap / 3 - 1) * dil; dx = (tap % 3 - 1) * dil; }
        int ii = i + dy, ww = w + dx;
        float v = 0.f;
        if ((unsigned)ii < 128u && (unsigned)ww < 128u) v = inb[(size_t)ci * HW + ii * 128 + ww];
        rb[r] = v;
    }
    for (int ch = 0; ch < nch; ch++) {
#pragma unroll
        for (int r = 0; r < 4; r++) {
            int e = (tid + r * 256) * 4;
            int kk = e >> 7, co = e & 127;
            *(uint4*)&As[kk][co] = ra[r];
        }
#pragma unroll
        for (int r = 0; r < 16; r++) {
            int e = tid + r * 256;
            int kk = e >> 7, w = e & 127;
            Bs[kk][w] = cvt1(rb[r]);
        }
        __syncthreads();
        if (ch + 1 < nch) {
            int k0 = (ch + 1) * 32;
#pragma unroll
            for (int r = 0; r < 4; r++) {
                int e = (tid + r * 256) * 4;
                int kk = e >> 7, co = e & 127;
                ra[r] = *(const uint4*)&wp[(size_t)(k0 + kk) * 128 + co];
            }
#pragma unroll
            for (int r = 0; r < 16; r++) {
                int e = tid + r * 256;
                int kk = e >> 7, w = e & 127;
                int kg = k0 + kk;
                int tap = kg >> 7, ci = kg & 127;
                int dy = 0, dx = 0;
                if (taps == 9) { dy = (tap / 3 - 1) * dil; dx = (tap % 3 - 1) * dil; }
                int ii = i + dy, ww = w + dx;
                float v = 0.f;
                if ((unsigned)ii < 128u && (unsigned)ww < 128u) v = inb[(size_t)ci * HW + ii * 128 + ww];
                rb[r] = v;
            }
        }
#pragma unroll
        for (int ks = 0; ks < 4; ks++) {
            unsigned b0[4], b1[4];
#pragma unroll
            for (int nt = 0; nt < 4; nt++) {
                b0[nt] = Bs[ks * 8 + tig][n_base + nt * 8 + gid];
                b1[nt] = Bs[ks * 8 + tig + 4][n_base + nt * 8 + gid];
            }
#pragma unroll
            for (int mt = 0; mt < 4; mt++) {
                int m = m_base + mt * 16;
                unsigned a0 = As[ks * 8 + tig][m + gid];
                unsigned a1 = As[ks * 8 + tig][m + 8 + gid];
                unsigned a2 = As[ks * 8 + tig + 4][m + gid];
                unsigned a3 = As[ks * 8 + tig + 4][m + 8 + gid];
#pragma unroll
                for (int nt = 0; nt < 4; nt++) mma_tf32(C[mt][nt], a0, a1, a2, a3, b0[nt], b1[nt]);
            }
        }
        __syncthreads();
    }
#pragma unroll
    for (int mt = 0; mt < 4; mt++)
#pragma unroll
        for (int half = 0; half < 2; half++) {
            int m = m_base + mt * 16 + gid + half * 8;
            size_t base = ((size_t)(b * 128 + m) * 128 + i) * 128;
#pragma unroll
            for (int nt = 0; nt < 4; nt++) {
                int n = n_base + nt * 8 + 2 * tig;
                float v0 = C[mt][nt][half * 2 + 0];
                float v1 = C[mt][nt][half * 2 + 1];
                if (resid) { v0 += resid[base + n]; v1 += resid[base + n + 1]; }
                float2 t = {v0, v1};
                *(float2*)&out[base + n] = t;
            }
        }
}

// ---------------- 1x1 conv with fused BN-ReLU-sum input ----------------------
__global__ __launch_bounds__(256) void conv_bnsum(const float* __restrict__ y1,
                                                  const float* __restrict__ y2,
                                                  const float* __restrict__ y3,
                                                  const float* __restrict__ ga1, const float* __restrict__ be1,
                                                  const float* __restrict__ ga2, const float* __restrict__ be2,
                                                  const float* __restrict__ ga3, const float* __restrict__ be3,
                                                  const float* __restrict__ wp,
                                                  const float* __restrict__ resid,
                                                  float* __restrict__ out) {
    __shared__ unsigned As[32][136];
    __shared__ unsigned Bs[32][136];
    __shared__ float sc[6][128];    // scale/shift per branch
    int bi = blockIdx.x;
    int b = bi >> 7, i = bi & 127;
    int tid = threadIdx.x, lane = tid & 31, wid = tid >> 5;
    int gid = lane >> 2, tig = lane & 3;
    int m_base = (wid >> 2) * 64, n_base = (wid & 3) * 32;
    if (tid < 128) {
        int c = tid;
        float m0 = g_stats[c],       r0 = g_stats[128 + c];
        float m1 = g_stats[256 + c], r1 = g_stats[256 + 128 + c];
        float m2 = g_stats[512 + c], r2 = g_stats[512 + 128 + c];
        float s0 = r0 * ga1[c], s1 = r1 * ga2[c], s2 = r2 * ga3[c];
        sc[0][c] = s0; sc[1][c] = be1[c] - m0 * s0;
        sc[2][c] = s1; sc[3][c] = be2[c] - m1 * s1;
        sc[4][c] = s2; sc[5][c] = be3[c] - m2 * s2;
    }
    __syncthreads();
    float C[4][4][4];
#pragma unroll
    for (int a = 0; a < 4; a++)
#pragma unroll
        for (int c = 0; c < 4; c++)
#pragma unroll
            for (int d = 0; d < 4; d++) C[a][c][d] = 0.f;
    size_t boff = (size_t)b * Cc * HW + (size_t)i * 128;
    const float* p1 = y1 + boff;
    const float* p2 = y2 + boff;
    const float* p3 = y3 + boff;
    uint4 ra[4];
    float rb[16];
#pragma unroll
    for (int r = 0; r < 4; r++) {
        int e = (tid + r * 256) * 4;
        int kk = e >> 7, co = e & 127;
        ra[r] = *(const uint4*)&wp[(size_t)kk * 128 + co];
    }
#pragma unroll
    for (int r = 0; r < 16; r++) {
        int e = tid + r * 256;
        int ci = e >> 7, w = e & 127;
        size_t off = (size_t)ci * HW + w;
        float v = fmaxf(p1[off] * sc[0][ci] + sc[1][ci], 0.f)
                + fmaxf(p2[off] * sc[2][ci] + sc[3][ci], 0.f)
                + fmaxf(p3[off] * sc[4][ci] + sc[5][ci], 0.f);
        rb[r] = v;
    }
    for (int ch = 0; ch < 4; ch++) {
#pragma unroll
        for (int r = 0; r < 4; r++) {
            int e = (tid + r * 256) * 4;
            int kk = e >> 7, co = e & 127;
            *(uint4*)&As[kk][co] = ra[r];
        }
#pragma unroll
        for (int r = 0; r < 16; r++) {
            int e = tid + r * 256;
            int kk = e >> 7, w = e & 127;
            Bs[kk][w] = cvt1(rb[r]);
        }
        __syncthreads();
        if (ch + 1 < 4) {
            int k0 = (ch + 1) * 32;
#pragma unroll
            for (int r = 0; r < 4; r++) {
                int e = (tid + r * 256) * 4;
                int kk = e >> 7, co = e & 127;
                ra[r] = *(const uint4*)&wp[(size_t)(k0 + kk) * 128 + co];
            }
#pragma unroll
            for (int r = 0; r < 16; r++) {
                int e = tid + r * 256;
                int kk = e >> 7, w = e & 127;
                int ci = k0 + kk;
                size_t off = (size_t)ci * HW + w;
                float v = fmaxf(p1[off] * sc[0][ci] + sc[1][ci], 0.f)
                        + fmaxf(p2[off] * sc[2][ci] + sc[3][ci], 0.f)
                        + fmaxf(p3[off] * sc[4][ci] + sc[5][ci], 0.f);
                rb[r] = v;
            }
        }
#pragma unroll
        for (int ks = 0; ks < 4; ks++) {
            unsigned b0[4], b1[4];
#pragma unroll
            for (int nt = 0; nt < 4; nt++) {
                b0[nt] = Bs[ks * 8 + tig][n_base + nt * 8 + gid];
                b1[nt] = Bs[ks * 8 + tig + 4][n_base + nt * 8 + gid];
            }
#pragma unroll
            for (int mt = 0; mt < 4; mt++) {
                int m = m_base + mt * 16;
                unsigned a0 = As[ks * 8 + tig][m + gid];
                unsigned a1 = As[ks * 8 + tig][m + 8 + gid];
                unsigned a2 = As[ks * 8 + tig + 4][m + gid];
                unsigned a3 = As[ks * 8 + tig + 4][m + 8 + gid];
#pragma unroll
                for (int nt = 0; nt < 4; nt++) mma_tf32(C[mt][nt], a0, a1, a2, a3, b0[nt], b1[nt]);
            }
        }
        __syncthreads();
    }
#pragma unroll
    for (int mt = 0; mt < 4; mt++)
#pragma unroll
        for (int half = 0; half < 2; half++) {
            int m = m_base + mt * 16 + gid + half * 8;
            size_t base = ((size_t)(b * 128 + m) * 128 + i) * 128;
#pragma unroll
            for (int nt = 0; nt < 4; nt++) {
                int n = n_base + nt * 8 + 2 * tig;
                float2 t;
                t.x = C[mt][nt][half * 2 + 0] + resid[base + n];
                t.y = C[mt][nt][half * 2 + 1] + resid[base + n + 1];
                *(float2*)&out[base + n] = t;
            }
        }
}

// ---------------- per-channel batch stats for three tensors ------------------
__global__ __launch_bounds__(256) void chan_stats3(const float* __restrict__ y1,
                                                   const float* __restrict__ y2,
                                                   const float* __restrict__ y3) {
    int bx = blockIdx.x;
    int which = bx >> 7, c = bx & 127;
    const float* y = which == 0 ? y1 : (which == 1 ? y2 : y3);
    int tid = threadIdx.x;
    float s = 0.f, sq = 0.f;
    for (int b = 0; b < Bb; b++) {
        const float* p = y + (size_t)(b * Cc + c) * HW;
        for (int idx = tid; idx < HW; idx += 256) { float v = p[idx]; s += v; sq += v * v; }
    }
    __shared__ float rs[256], rq[256];
    rs[tid] = s; rq[tid] = sq;
    __syncthreads();
    for (int o = 128; o; o >>= 1) {
        if (tid < o) { rs[tid] += rs[tid + o]; rq[tid] += rq[tid + o]; }
        __syncthreads();
    }
    if (tid == 0) {
        float inv = 1.f / (float)(Bb * HW);
        float m = rs[0] * inv;
        float var = rq[0] * inv - m * m;
        g_stats[which * 256 + c] = m;
        g_stats[which * 256 + 128 + c] = rsqrtf(var + 1e-5f);
    }
}

// ---------------- six depthwise convs with fused LN on load ------------------
__global__ __launch_bounds__(256) void dw_ln(const float* __restrict__ x,
    const float* __restrict__ mu, const float* __restrict__ rs,
    const float* __restrict__ lw, const float* __restrict__ lb,
    const float* __restrict__ w1, const float* __restrict__ b1,
    const float* __restrict__ w2, const float* __restrict__ b2,
    const float* __restrict__ w3, const float* __restrict__ b3,
    const float* __restrict__ w4, const float* __restrict__ b4,
    const float* __restrict__ w5, const float* __restrict__ b5,
    const float* __restrict__ w6, const float* __restrict__ b6,
    float* __restrict__ out) {
    extern __shared__ float plane[];
    int bc = blockIdx.x;
    int b = bc >> 7, c = bc & 127;
    const float* p = x + (size_t)bc * HW;
    const float* mup = mu + (size_t)b * HW;
    const float* rsp = rs + (size_t)b * HW;
    float lwc = lw[c], lbc = lb[c];
    for (int idx = threadIdx.x; idx < HW; idx += 256)
        plane[idx] = (p[idx] - mup[idx]) * rsp[idx] * lwc + lbc;
    float f1[5], f2[5], f4[9], f5[7], f6[7];
#pragma unroll
    for (int j = 0; j < 5; j++) { f1[j] = w1[c * 5 + j]; f2[j] = w2[c * 5 + j]; }
#pragma unroll
    for (int j = 0; j < 9; j++) f4[j] = w4[c * 9 + j];
#pragma unroll
    for (int j = 0; j < 7; j++) { f5[j] = w5[c * 7 + j]; f6[j] = w6[c * 7 + j]; }
    float f3 = w3[c];
    float bias = b1[c] + b2[c] + b3[c] + b4[c] + b5[c] + b6[c];
    __syncthreads();
    for (int idx = threadIdx.x; idx < HW; idx += 256) {
        int i = idx >> 7, w = idx & 127;
        float acc = bias + f3 * plane[idx];
#pragma unroll
        for (int j = 0; j < 5; j++) { int ww = w + j - 2; if ((unsigned)ww < Ww) acc += f1[j] * plane[i * Ww + ww]; }
#pragma unroll
        for (int j = 0; j < 5; j++) { int ii = i + j - 2; if ((unsigned)ii < Hh) acc += f2[j] * plane[ii * Ww + w]; }
#pragma unroll
        for (int pq = 0; pq < 9; pq++) {
            int ii = i + pq / 3 - 1, ww = w + pq % 3 - 1;
            if ((unsigned)ii < Hh && (unsigned)ww < Ww) acc += f4[pq] * plane[ii * Ww + ww];
        }
#pragma unroll
        for (int j = 0; j < 7; j++) { int ww = w + j - 3; if ((unsigned)ww < Ww) acc += f5[j] * plane[i * Ww + ww]; }
#pragma unroll
        for (int j = 0; j < 7; j++) { int ii = i + j - 3; if ((unsigned)ii < Hh) acc += f6[j] * plane[ii * Ww + w]; }
        out[(size_t)bc * HW + idx] = acc;
    }
}

// ---------------- rearranges -------------------------------------------------
// hwc with fused row-norm (block owns one full dst row)
__global__ __launch_bounds__(256) void hwc_n_kernel(const float* __restrict__ src,
                                                    float* __restrict__ dst,
                                                    float* __restrict__ nrm) {
    int r = blockIdx.x;
    int i = r & 127, bh = r >> 7;
    int b = bh >> 3, hd = bh & 7;
    __shared__ float tile[16][129];
    __shared__ float red[256];
    float sq = 0.f;
    for (int idx = threadIdx.x; idx < 2048; idx += 256) {
        int c = idx >> 7, w = idx & 127;
        float v = src[((size_t)(b * Cc + hd * 16 + c) * Hh + i) * Ww + w];
        tile[c][w] = v;
        sq += v * v;
    }
    red[threadIdx.x] = sq;
    __syncthreads();
    for (int o = 128; o; o >>= 1) { if (threadIdx.x < o) red[threadIdx.x] += red[threadIdx.x + o]; __syncthreads(); }
    if (threadIdx.x == 0) nrm[bh * 128 + i] = fmaxf(sqrtf(red[0]), 1e-12f);
    float* d = dst + ((size_t)bh * Hh + i) * DD;
    for (int idx = threadIdx.x; idx < 2048; idx += 256) {
        int w = idx >> 4, c = idx & 15;
        d[idx] = tile[c][w];
    }
}

__global__ __launch_bounds__(256) void whc_kernel(const float* __restrict__ src, float* __restrict__ dst) {
    int r = blockIdx.x;
    int i = r & 127, bh = r >> 7;
    int b = bh >> 3, hd = bh & 7;
    __shared__ float tile[16][129];
    for (int idx = threadIdx.x; idx < 2048; idx += 256) {
        int c = idx >> 7, w = idx & 127;
        tile[c][w] = src[((size_t)(b * Cc + hd * 16 + c) * Hh + i) * Ww + w];
    }
    __syncthreads();
    float* d = dst + (size_t)bh * Ww * DD + i * 16;
    for (int idx = threadIdx.x; idx < 2048; idx += 256) {
        int w = idx >> 4, c = idx & 15;
        d[(size_t)w * DD + c] = tile[c][w];
    }
}

__global__ __launch_bounds__(256) void rownorm(const float* __restrict__ buf, float* __restrict__ nrm) {
    int r = blockIdx.x, tid = threadIdx.x;
    const float* p = buf + (size_t)r * DD;
    float sq = 0.f;
    for (int idx = tid; idx < DD; idx += 256) { float v = p[idx]; sq += v * v; }
    __shared__ float rq[256];
    rq[tid] = sq;
    __syncthreads();
    for (int o = 128; o; o >>= 1) { if (tid < o) rq[tid] += rq[tid + o]; __syncthreads(); }
    if (tid == 0) nrm[r] = fmaxf(sqrtf(rq[0]), 1e-12f);
}

// ---------------- QK^T + softmax (tf32) --------------------------------------
__global__ __launch_bounds__(256) void qk_tf32(const float* __restrict__ Q,
                                               const float* __restrict__ K,
                                               const float* __restrict__ qn,
                                               const float* __restrict__ kn,
                                               float* __restrict__ A) {
    __shared__ float Lsm[64][132];
    unsigned* sb = (unsigned*)Lsm;
    unsigned (*Qs)[36] = (unsigned(*)[36])sb;
    unsigned (*Ks)[36] = (unsigned(*)[36])(sb + 64 * 36);
    int bh = blockIdx.x;
    int m0 = blockIdx.y * 64;
    const float* q = Q + (size_t)(bh * 128 + m0) * DD;
    const float* k = K + (size_t)bh * 128 * DD;
    int tid = threadIdx.x, lane = tid & 31, wid = tid >> 5;
    int gid = lane >> 2, tig = lane & 3;
    int m_base = (wid >> 2) * 32, n_base = (wid & 3) * 32;
    float C[2][4][4];
#pragma unroll
    for (int a = 0; a < 2; a++)
#pragma unroll
        for (int c = 0; c < 4; c++)
#pragma unroll
            for (int d = 0; d < 4; d++) C[a][c][d] = 0.f;
    uint4 pq[2], pk[4];
#pragma unroll
    for (int r = 0; r < 2; r++) {
        int e = (tid + r * 256) * 4;
        int m = e >> 5, kk = e & 31;
        pq[r] = cvt4(*(const float4*)&q[(size_t)m * DD + kk]);
    }
#pragma unroll
    for (int r = 0; r < 4; r++) {
        int e = (tid + r * 256) * 4;
        int n = e >> 5, kk = e & 31;
        pk[r] = cvt4(*(const float4*)&k[(size_t)n * DD + kk]);
    }
    for (int ch = 0; ch < 64; ch++) {
#pragma unroll
        for (int r = 0; r < 2; r++) {
            int e = (tid + r * 256) * 4;
            int m = e >> 5, kk = e & 31;
            *(uint4*)&Qs[m][kk] = pq[r];
        }
#pragma unroll
        for (int r = 0; r < 4; r++) {
            int e = (tid + r * 256) * 4;
            int n = e >> 5, kk = e & 31;
            *(uint4*)&Ks[n][kk] = pk[r];
        }
        __syncthreads();
        if (ch + 1 < 64) {
            int k0 = (ch + 1) * 32;
#pragma unroll
            for (int r = 0; r < 2; r++) {
                int e = (tid + r * 256) * 4;
                int m = e >> 5, kk = e & 31;
                pq[r] = cvt4(*(const float4*)&q[(size_t)m * DD + k0 + kk]);
            }
#pragma unroll
            for (int r = 0; r < 4; r++) {
                int e = (tid + r * 256) * 4;
                int n = e >> 5, kk = e & 31;
                pk[r] = cvt4(*(const float4*)&k[(size_t)n * DD + k0 + kk]);
            }
        }
#pragma unroll
        for (int ks = 0; ks < 4; ks++) {
            unsigned b0[4], b1[4];
#pragma unroll
            for (int nt = 0; nt < 4; nt++) {
                b0[nt] = Ks[n_base + nt * 8 + gid][ks * 8 + tig];
                b1[nt] = Ks[n_base + nt * 8 + gid][ks * 8 + tig + 4];
            }
#pragma unroll
            for (int mt = 0; mt < 2; mt++) {
                int m = m_base + mt * 16;
                unsigned a0 = Qs[m + gid][ks * 8 + tig];
                unsigned a1 = Qs[m + 8 + gid][ks * 8 + tig];
                unsigned a2 = Qs[m + gid][ks * 8 + tig + 4];
                unsigned a3 = Qs[m + 8 + gid][ks * 8 + tig + 4];
#pragma unroll
                for (int nt = 0; nt < 4; nt++) mma_tf32(C[mt][nt], a0, a1, a2, a3, b0[nt], b1[nt]);
            }
        }
        __syncthreads();
    }
#pragma unroll
    for (int mt = 0; mt < 2; mt++)
#pragma unroll
        for (int half = 0; half < 2; half++) {
            int m = m_base + mt * 16 + gid + half * 8;
            float invq = 1.f / qn[bh * 128 + m0 + m];
#pragma unroll
            for (int nt = 0; nt < 4; nt++) {
                int n = n_base + nt * 8 + 2 * tig;
                Lsm[m][n]     = C[mt][nt][half * 2 + 0] * invq / kn[bh * 128 + n];
                Lsm[m][n + 1] = C[mt][nt][half * 2 + 1] * invq / kn[bh * 128 + n + 1];
            }
        }
    __syncthreads();
    {
        int row = wid * 8;
        for (int rr = 0; rr < 8; rr++, row++) {
            float v[4];
#pragma unroll
            for (int j = 0; j < 4; j++) v[j] = Lsm[row][lane + j * 32];
            float mx = fmaxf(fmaxf(v[0], v[1]), fmaxf(v[2], v[3]));
            for (int o = 16; o; o >>= 1) mx = fmaxf(mx, __shfl_xor_sync(0xffffffffu, mx, o));
            float sum = 0.f;
#pragma unroll
            for (int j = 0; j < 4; j++) { v[j] = __expf(v[j] - mx); sum += v[j]; }
            for (int o = 16; o; o >>= 1) sum += __shfl_xor_sync(0xffffffffu, sum, o);
            float inv = 1.f / sum;
            float* ap = A + ((size_t)(bh * 128 + m0 + row)) * 128;
#pragma unroll
            for (int j = 0; j < 4; j++) ap[lane + j * 32] = v[j] * inv;
        }
    }
}

// ---------------- A @ V + normalized Q ---------------------------------------
__global__ __launch_bounds__(256) void av_tf32(const float* __restrict__ A,
                                               const float* __restrict__ V,
                                               const float* __restrict__ Q,
                                               const float* __restrict__ qn,
                                               float* __restrict__ out) {
    __shared__ unsigned Ap[128][36];
    __shared__ unsigned Vs[32][136];
    int bh = blockIdx.x;
    int n0 = blockIdx.y * 128;
    const float* a = A + (size_t)bh * 128 * 128;
    const float* v = V + (size_t)bh * 128 * DD + n0;
    int tid = threadIdx.x, lane = tid & 31, wid = tid >> 5;
    int gid = lane >> 2, tig = lane & 3;
    int m_base = (wid >> 2) * 64, n_base = (wid & 3) * 32;
    float C[4][4][4];
#pragma unroll
    for (int x = 0; x < 4; x++)
#pragma unroll
        for (int y = 0; y < 4; y++)
#pragma unroll
            for (int d = 0; d < 4; d++) C[x][y][d] = 0.f;
    uint4 pa[4], pv[4];
#pragma unroll
    for (int r = 0; r < 4; r++) {
        int e = (tid + r * 256) * 4;
        int m = e >> 5, kk = e & 31;
        pa[r] = cvt4(*(const float4*)&a[(size_t)m * 128 + kk]);
    }
#pragma unroll
    for (int r = 0; r < 4; r++) {
        int e = (tid + r * 256) * 4;
        int kk = e >> 7, n = e & 127;
        pv[r] = cvt4(*(const float4*)&v[(size_t)kk * DD + n]);
    }
    for (int ch = 0; ch < 4; ch++) {
#pragma unroll
        for (int r = 0; r < 4; r++) {
            int e = (tid + r * 256) * 4;
            int m = e >> 5, kk = e & 31;
            *(uint4*)&Ap[m][kk] = pa[r];
        }
#pragma unroll
        for (int r = 0; r < 4; r++) {
            int e = (tid + r * 256) * 4;
            int kk = e >> 7, n = e & 127;
            *(uint4*)&Vs[kk][n] = pv[r];
        }
        __syncthreads();
        if (ch + 1 < 4) {
            int k0 = (ch + 1) * 32;
#pragma unroll
            for (int r = 0; r < 4; r++) {
                int e = (tid + r * 256) * 4;
                int m = e >> 5, kk = e & 31;
                pa[r] = cvt4(*(const float4*)&a[(size_t)m * 128 + k0 + kk]);
            }
#pragma unroll
            for (int r = 0; r < 4; r++) {
                int e = (tid + r * 256) * 4;
                int kk = e >> 7, n = e & 127;
                pv[r] = cvt4(*(const float4*)&v[(size_t)(k0 + kk) * DD + n]);
            }
        }
#pragma unroll
        for (int ks = 0; ks < 4; ks++) {
            unsigned b0[4], b1[4];
#pragma unroll
            for (int nt = 0; nt < 4; nt++) {
                b0[nt] = Vs[ks * 8 + tig][n_base + nt * 8 + gid];
                b1[nt] = Vs[ks * 8 + tig + 4][n_base + nt * 8 + gid];
            }
#pragma unroll
            for (int mt = 0; mt < 4; mt++) {
                int m = m_base + mt * 16;
                unsigned a0 = Ap[m + gid][ks * 8 + tig];
                unsigned a1 = Ap[m + 8 + gid][ks * 8 + tig];
                unsigned a2 = Ap[m + gid][ks * 8 + tig + 4];
                unsigned a3 = Ap[m + 8 + gid][ks * 8 + tig + 4];
#pragma unroll
                for (int nt = 0; nt < 4; nt++) mma_tf32(C[mt][nt], a0, a1, a2, a3, b0[nt], b1[nt]);
            }
        }
        __syncthreads();
    }
#pragma unroll
    for (int mt = 0; mt < 4; mt++)
#pragma unroll
        for (int half = 0; half < 2; half++) {
            int m = m_base + mt * 16 + gid + half * 8;
            float invq = 1.f / qn[bh * 128 + m];
            const float* qp = Q + ((size_t)(bh * 128 + m)) * DD + n0;
            float* op = out + ((size_t)(bh * 128 + m)) * DD + n0;
#pragma unroll
            for (int nt = 0; nt < 4; nt++) {
                int n = n_base + nt * 8 + 2 * tig;
                float2 t;
                t.x = C[mt][nt][half * 2 + 0] + qp[n] * invq;
                t.y = C[mt][nt][half * 2 + 1] + qp[n + 1] * invq;
                *(float2*)&op[n] = t;
            }
        }
}

// ---------------- merge o3+o4 back to NCHW -----------------------------------
__global__ __launch_bounds__(256) void merge_kernel(const float* __restrict__ o3,
                                                    const float* __restrict__ o4,
                                                    float* __restrict__ out) {
    int r = blockIdx.x;
    int i = r & 127, bh = r >> 7;
    int b = bh >> 3, hd = bh & 7;
    __shared__ float t3[128][17];
    __shared__ float t4[128][17];
    const float* p3 = o3 + ((size_t)bh * Hh + i) * DD;
    const float* p4 = o4 + (size_t)bh * Ww * DD + i * 16;
    for (int idx = threadIdx.x; idx < 2048; idx += 256) {
        int w = idx >> 4, c = idx & 15;
        t3[w][c] = p3[idx];
        t4[w][c] = p4[(size_t)w * DD + c];
    }
    __syncthreads();
    for (int idx = threadIdx.x; idx < 2048; idx += 256) {
        int c = idx >> 7, w = idx & 127;
        out[((size_t)(b * Cc + hd * 16 + c) * Hh + i) * Ww + w] = t3[w][c] + t4[w][c];
    }
}

// ---------------- launch -----------------------------------------------------
extern "C" void kernel_launch(void* const* d_in, const int* in_sizes, int n_in,
                              void* d_out, int out_size) {
    const float* x    = (const float*)d_in[0];
    const float* ln_w = (const float*)d_in[1];
    const float* ln_b = (const float*)d_in[2];
    const float* wd1  = (const float*)d_in[3];
    const float* gd1  = (const float*)d_in[4];
    const float* bd1  = (const float*)d_in[5];
    const float* wd2  = (const float*)d_in[6];
    const float* gd2  = (const float*)d_in[7];
    const float* bd2  = (const float*)d_in[8];
    const float* wd3  = (const float*)d_in[9];
    const float* gd3  = (const float*)d_in[10];
    const float* bd3  = (const float*)d_in[11];
    const float* w_out1 = (const float*)d_in[12];
    const float* w1 = (const float*)d_in[13]; const float* b1 = (const float*)d_in[14];
    const float* w2 = (const float*)d_in[15]; const float* b2 = (const float*)d_in[16];
    const float* w3 = (const float*)d_in[17]; const float* b3 = (const float*)d_in[18];
    const float* w4 = (const float*)d_in[19]; const float* b4 = (const float*)d_in[20];
    const float* w5 = (const float*)d_in[21]; const float* b5 = (const float*)d_in[22];
    const float* w6 = (const float*)d_in[23]; const float* b6 = (const float*)d_in[24];
    const float* w_out2 = (const float*)d_in[25];
    float* outp = (float*)d_out;

    float *p_x1, *p_y, *p_s, *p_out2, *p_hwc1, *p_whc1, *p_whc2;
    float *p_A1, *p_A2, *p_n1, *p_n2, *p_n3, *p_mu, *p_rs;
    float *p_wp1, *p_wp2, *p_wp3, *p_wpo1, *p_wpo2;
    cudaGetSymbolAddress((void**)&p_x1, g_x1);
    cudaGetSymbolAddress((void**)&p_y, g_y);
    cudaGetSymbolAddress((void**)&p_s, g_s);
    cudaGetSymbolAddress((void**)&p_out2, g_out2);
    cudaGetSymbolAddress((void**)&p_hwc1, g_hwc1);
    cudaGetSymbolAddress((void**)&p_whc1, g_whc1);
    cudaGetSymbolAddress((void**)&p_whc2, g_whc2);
    cudaGetSymbolAddress((void**)&p_A1, g_A1);
    cudaGetSymbolAddress((void**)&p_A2, g_A2);
    cudaGetSymbolAddress((void**)&p_n1, g_n_hwc1);
    cudaGetSymbolAddress((void**)&p_n2, g_n_whc1);
    cudaGetSymbolAddress((void**)&p_n3, g_n_whc2);
    cudaGetSymbolAddress((void**)&p_mu, g_mu);
    cudaGetSymbolAddress((void**)&p_rs, g_rs);
    cudaGetSymbolAddress((void**)&p_wp1, g_wp1);
    cudaGetSymbolAddress((void**)&p_wp2, g_wp2);
    cudaGetSymbolAddress((void**)&p_wp3, g_wp3);
    cudaGetSymbolAddress((void**)&p_wpo1, g_wpo1);
    cudaGetSymbolAddress((void**)&p_wpo2, g_wpo2);

    cudaFuncSetAttribute(dw_ln, cudaFuncAttributeMaxDynamicSharedMemorySize, HW * 4);

    // packs (launches 1-5)
    pack_w<<<64, 256>>>(wd1, p_wp1, 1);
    pack_w<<<576, 256>>>(wd2, p_wp2, 9);
    pack_w<<<576, 256>>>(wd3, p_wp3, 9);
    pack_w<<<64, 256>>>(w_out1, p_wpo1, 1);
    pack_w<<<64, 256>>>(w_out2, p_wpo2, 1);

    // launch #6 (profiled by ncu -s 5 -c 1): the heavy dilated conv
    conv_tf32<<<Bb * Hh, 256>>>(x, p_wp2, nullptr, p_hwc1, 9, 6);   // y2
    conv_tf32<<<Bb * Hh, 256>>>(x, p_wp3, nullptr, p_whc1, 9, 12);  // y3
    conv_tf32<<<Bb * Hh, 256>>>(x, p_wp1, nullptr, p_y, 1, 1);      // y1
    ln_stats<<<Bb * Hh, 128>>>(x, p_mu, p_rs);
    chan_stats3<<<3 * Cc, 256>>>(p_y, p_hwc1, p_whc1);
    // out2 = conv1x1(bn-relu-sum, w_out1) + x   (BN fused into loader)
    conv_bnsum<<<Bb * Hh, 256>>>(p_y, p_hwc1, p_whc1, gd1, bd1, gd2, bd2, gd3, bd3,
                                 p_wpo1, x, p_out2);

    // att = six depthwise convs on LN(x) (LN fused into plane load) -> g_x1
    dw_ln<<<Bb * Cc, 256, HW * 4>>>(x, p_mu, p_rs, ln_w, ln_b,
                                    w1, b1, w2, b2, w3, b3, w4, b4, w5, b5, w6, b6, p_x1);
    // out1 = conv1x1(att, w_out2) -> g_s
    conv_tf32<<<Bb * Hh, 256>>>(p_x1, p_wpo2, nullptr, p_s, 1, 1);

    // rearranges + norms
    hwc_n_kernel<<<BH * Hh, 256>>>(p_s, p_hwc1, p_n1);
    whc_kernel<<<BH * Hh, 256>>>(p_s, p_whc1);
    whc_kernel<<<BH * Hh, 256>>>(p_out2, p_whc2);
    rownorm<<<BH * Ww, 256>>>(p_whc1, p_n2);
    rownorm<<<BH * Ww, 256>>>(p_whc2, p_n3);

    // attention
    qk_tf32<<<dim3(BH, 2), 256>>>(p_whc2, p_hwc1, p_n3, p_n1, p_A1);
    qk_tf32<<<dim3(BH, 2), 256>>>(p_whc1, p_whc2, p_n2, p_n3, p_A2);
    av_tf32<<<dim3(BH, 16), 256>>>(p_A1, p_hwc1, p_whc2, p_n3, p_x1);
    av_tf32<<<dim3(BH, 16), 256>>>(p_A2, p_whc2, p_whc1, p_n2, p_y);

    // merge + final conv
    merge_kernel<<<BH * Hh, 256>>>(p_x1, p_y, p_out2);
    conv_tf32<<<Bb * Hh, 256>>>(p_out2, p_wpo2, x, outp, 1, 1);
}

// round 4
// speedup vs baseline: 1.4824x; 1.4824x over previous
#include <cuda_runtime.h>

#define Bb 8
#define Cc 128
#define Hh 128
#define Ww 128
#define HW 16384
#define NELEM (Bb*Cc*HW)
#define DD 2048
#define BH 64

// ---------------- scratch ----------------------------------------------------
__device__ float g_x1[NELEM];     // LN output; later out1
__device__ float g_y[NELEM];      // y1; later out4
__device__ float g_s[NELEM];      // bn-relu sum; later out3
__device__ float g_out2[NELEM];   // out2; later merged o3+o4
__device__ float g_hwc1[NELEM];   // y2 first, then hwc(out1)
__device__ float g_whc1[NELEM];   // y3 first, then whc(out1)
__device__ float g_whc2[NELEM];   // att first, then whc(out2)
__device__ float g_A1[BH*Hh*Ww];
__device__ float g_A2[BH*Hh*Ww];
__device__ float g_n_hwc1[BH*Hh];
__device__ float g_n_whc1[BH*Ww];
__device__ float g_n_whc2[BH*Ww];
__device__ float g_stats[6*Cc];
__device__ float g_wp1[Cc*Cc];
__device__ float g_wp2[9*Cc*Cc];
__device__ float g_wp3[9*Cc*Cc];
__device__ float g_wpo1[Cc*Cc];
__device__ float g_wpo2[Cc*Cc];

// ---------------- tf32 helpers ----------------------------------------------
__device__ __forceinline__ unsigned cvt1(float f) {
    unsigned u; asm("cvt.rna.tf32.f32 %0, %1;" : "=r"(u) : "f"(f)); return u;
}
__device__ __forceinline__ uint4 cvt4(float4 f) {
    uint4 u;
    asm("cvt.rna.tf32.f32 %0, %1;" : "=r"(u.x) : "f"(f.x));
    asm("cvt.rna.tf32.f32 %0, %1;" : "=r"(u.y) : "f"(f.y));
    asm("cvt.rna.tf32.f32 %0, %1;" : "=r"(u.z) : "f"(f.z));
    asm("cvt.rna.tf32.f32 %0, %1;" : "=r"(u.w) : "f"(f.w));
    return u;
}
__device__ __forceinline__ void mma_tf32(float* c, unsigned a0, unsigned a1,
                                         unsigned a2, unsigned a3,
                                         unsigned b0, unsigned b1) {
    asm volatile("mma.sync.aligned.m16n8k8.row.col.f32.tf32.tf32.f32 "
                 "{%0,%1,%2,%3}, {%4,%5,%6,%7}, {%8,%9}, {%0,%1,%2,%3};"
                 : "+f"(c[0]), "+f"(c[1]), "+f"(c[2]), "+f"(c[3])
                 : "r"(a0), "r"(a1), "r"(a2), "r"(a3), "r"(b0), "r"(b1));
}

// ---------------- single-launch weight pack ----------------------------------
__device__ __forceinline__ void pack_one(const float* __restrict__ w,
                                         float* __restrict__ wp, int taps, int idx) {
    int co = idx / (Cc * taps);
    int rem = idx % (Cc * taps);
    int ci = rem / taps;
    int tap = rem % taps;
    wp[(tap * Cc + ci) * Cc + co] = __uint_as_float(cvt1(w[idx]));
}
__global__ void pack_all(const float* __restrict__ wd1, const float* __restrict__ wd2,
                         const float* __restrict__ wd3, const float* __restrict__ wo1,
                         const float* __restrict__ wo2) {
    int idx = blockIdx.x * 256 + threadIdx.x;
    if (idx < 16384)            pack_one(wd1, g_wp1, 1, idx);
    else if (idx < 163840)      pack_one(wd2, g_wp2, 9, idx - 16384);
    else if (idx < 311296)      pack_one(wd3, g_wp3, 9, idx - 163840);
    else if (idx < 327680)      pack_one(wo1, g_wpo1, 1, idx - 311296);
    else if (idx < 344064)      pack_one(wo2, g_wpo2, 1, idx - 327680);
}

// ---------------- LayerNorm over channels ------------------------------------
__global__ __launch_bounds__(128) void ln_kernel(const float* __restrict__ x,
                                                 const float* __restrict__ lw,
                                                 const float* __restrict__ lb,
                                                 float* __restrict__ o) {
    int bi = blockIdx.x;
    int b = bi >> 7, i = bi & 127;
    int w = threadIdx.x;
    const float* p = x + (size_t)b * Cc * HW + i * Ww + w;
    float s = 0.f, sq = 0.f;
    for (int c = 0; c < Cc; c++) { float v = p[(size_t)c * HW]; s += v; sq += v * v; }
    float mu = s * (1.f / Cc);
    float var = sq * (1.f / Cc) - mu * mu;
    float r = rsqrtf(var + 1e-5f);
    float* op = o + (size_t)b * Cc * HW + i * Ww + w;
    for (int c = 0; c < Cc; c++) {
        float v = p[(size_t)c * HW];
        op[(size_t)c * HW] = (v - mu) * r * lw[c] + lb[c];
    }
}

// ---------------- conv as implicit-im2col tf32 GEMM --------------------------
__global__ __launch_bounds__(256) void conv_tf32(const float* __restrict__ in,
                                                 const float* __restrict__ wp,
                                                 const float* __restrict__ resid,
                                                 float* __restrict__ out,
                                                 int taps, int dil) {
    __shared__ unsigned As[32][136];
    __shared__ unsigned Bs[32][136];
    int bi = blockIdx.x;
    int b = bi >> 7, i = bi & 127;
    int tid = threadIdx.x, lane = tid & 31, wid = tid >> 5;
    int gid = lane >> 2, tig = lane & 3;
    int m_base = (wid >> 2) * 64, n_base = (wid & 3) * 32;
    float C[4][4][4];
#pragma unroll
    for (int a = 0; a < 4; a++)
#pragma unroll
        for (int c = 0; c < 4; c++)
#pragma unroll
            for (int d = 0; d < 4; d++) C[a][c][d] = 0.f;
    int K = taps * 128, nch = K >> 5;
    const float* inb = in + (size_t)b * Cc * HW;
    uint4 ra[4];
    float rb[16];
#pragma unroll
    for (int r = 0; r < 4; r++) {
        int e = (tid + r * 256) * 4;
        int kk = e >> 7, co = e & 127;
        ra[r] = *(const uint4*)&wp[(size_t)kk * 128 + co];
    }
#pragma unroll
    for (int r = 0; r < 16; r++) {
        int e = tid + r * 256;
        int kk = e >> 7, w = e & 127;
        int tap = kk >> 7, ci = kk & 127;
        int dy = 0, dx = 0;
        if (taps == 9) { dy = (tap / 3 - 1) * dil; dx = (tap % 3 - 1) * dil; }
        int ii = i + dy, ww = w + dx;
        float v = 0.f;
        if ((unsigned)ii < 128u && (unsigned)ww < 128u) v = inb[(size_t)ci * HW + ii * 128 + ww];
        rb[r] = v;
    }
    for (int ch = 0; ch < nch; ch++) {
#pragma unroll
        for (int r = 0; r < 4; r++) {
            int e = (tid + r * 256) * 4;
            int kk = e >> 7, co = e & 127;
            *(uint4*)&As[kk][co] = ra[r];
        }
#pragma unroll
        for (int r = 0; r < 16; r++) {
            int e = tid + r * 256;
            int kk = e >> 7, w = e & 127;
            Bs[kk][w] = cvt1(rb[r]);
        }
        __syncthreads();
        if (ch + 1 < nch) {
            int k0 = (ch + 1) * 32;
#pragma unroll
            for (int r = 0; r < 4; r++) {
                int e = (tid + r * 256) * 4;
                int kk = e >> 7, co = e & 127;
                ra[r] = *(const uint4*)&wp[(size_t)(k0 + kk) * 128 + co];
            }
#pragma unroll
            for (int r = 0; r < 16; r++) {
                int e = tid + r * 256;
                int kk = e >> 7, w = e & 127;
                int kg = k0 + kk;
                int tap = kg >> 7, ci = kg & 127;
                int dy = 0, dx = 0;
                if (taps == 9) { dy = (tap / 3 - 1) * dil; dx = (tap % 3 - 1) * dil; }
                int ii = i + dy, ww = w + dx;
                float v = 0.f;
                if ((unsigned)ii < 128u && (unsigned)ww < 128u) v = inb[(size_t)ci * HW + ii * 128 + ww];
                rb[r] = v;
            }
        }
#pragma unroll
        for (int ks = 0; ks < 4; ks++) {
            unsigned b0[4], b1[4];
#pragma unroll
            for (int nt = 0; nt < 4; nt++) {
                b0[nt] = Bs[ks * 8 + tig][n_base + nt * 8 + gid];
                b1[nt] = Bs[ks * 8 + tig + 4][n_base + nt * 8 + gid];
            }
#pragma unroll
            for (int mt = 0; mt < 4; mt++) {
                int m = m_base + mt * 16;
                unsigned a0 = As[ks * 8 + tig][m + gid];
                unsigned a1 = As[ks * 8 + tig][m + 8 + gid];
                unsigned a2 = As[ks * 8 + tig + 4][m + gid];
                unsigned a3 = As[ks * 8 + tig + 4][m + 8 + gid];
#pragma unroll
                for (int nt = 0; nt < 4; nt++) mma_tf32(C[mt][nt], a0, a1, a2, a3, b0[nt], b1[nt]);
            }
        }
        __syncthreads();
    }
#pragma unroll
    for (int mt = 0; mt < 4; mt++)
#pragma unroll
        for (int half = 0; half < 2; half++) {
            int m = m_base + mt * 16 + gid + half * 8;
            size_t base = ((size_t)(b * 128 + m) * 128 + i) * 128;
#pragma unroll
            for (int nt = 0; nt < 4; nt++) {
                int n = n_base + nt * 8 + 2 * tig;
                float v0 = C[mt][nt][half * 2 + 0];
                float v1 = C[mt][nt][half * 2 + 1];
                if (resid) { v0 += resid[base + n]; v1 += resid[base + n + 1]; }
                float2 t = {v0, v1};
                *(float2*)&out[base + n] = t;
            }
        }
}

// ---------------- per-channel batch stats for three tensors ------------------
__global__ __launch_bounds__(256) void chan_stats3(const float* __restrict__ y1,
                                                   const float* __restrict__ y2,
                                                   const float* __restrict__ y3) {
    int bx = blockIdx.x;
    int which = bx >> 7, c = bx & 127;
    const float* y = which == 0 ? y1 : (which == 1 ? y2 : y3);
    int tid = threadIdx.x;
    float s = 0.f, sq = 0.f;
    for (int b = 0; b < Bb; b++) {
        const float* p = y + (size_t)(b * Cc + c) * HW;
        for (int idx = tid; idx < HW; idx += 256) { float v = p[idx]; s += v; sq += v * v; }
    }
    __shared__ float rs[256], rq[256];
    rs[tid] = s; rq[tid] = sq;
    __syncthreads();
    for (int o = 128; o; o >>= 1) {
        if (tid < o) { rs[tid] += rs[tid + o]; rq[tid] += rq[tid + o]; }
        __syncthreads();
    }
    if (tid == 0) {
        float inv = 1.f / (float)(Bb * HW);
        float m = rs[0] * inv;
        float var = rq[0] * inv - m * m;
        g_stats[which * 256 + c] = m;
        g_stats[which * 256 + 128 + c] = rsqrtf(var + 1e-5f);
    }
}

__global__ __launch_bounds__(256) void bnrelu3(const float* __restrict__ y1,
                                               const float* __restrict__ y2,
                                               const float* __restrict__ y3,
                                               const float* __restrict__ g1, const float* __restrict__ b1,
                                               const float* __restrict__ g2, const float* __restrict__ b2,
                                               const float* __restrict__ g3, const float* __restrict__ b3,
                                               float* __restrict__ s) {
    int idx = blockIdx.x * 256 + threadIdx.x;
    int c = (idx >> 14) & 127;
    float v1 = fmaxf((y1[idx] - g_stats[c]) * g_stats[128 + c] * g1[c] + b1[c], 0.f);
    float v2 = fmaxf((y2[idx] - g_stats[256 + c]) * g_stats[256 + 128 + c] * g2[c] + b2[c], 0.f);
    float v3 = fmaxf((y3[idx] - g_stats[512 + c]) * g_stats[512 + 128 + c] * g3[c] + b3[c], 0.f);
    s[idx] = v1 + v2 + v3;
}

// ---------------- six depthwise convs fused ----------------------------------
__global__ __launch_bounds__(256) void dw_kernel(const float* __restrict__ x1,
    const float* __restrict__ w1, const float* __restrict__ b1,
    const float* __restrict__ w2, const float* __restrict__ b2,
    const float* __restrict__ w3, const float* __restrict__ b3,
    const float* __restrict__ w4, const float* __restrict__ b4,
    const float* __restrict__ w5, const float* __restrict__ b5,
    const float* __restrict__ w6, const float* __restrict__ b6,
    float* __restrict__ out) {
    extern __shared__ float plane[];
    int bc = blockIdx.x;
    int c = bc & 127;
    const float* p = x1 + (size_t)bc * HW;
    for (int idx = threadIdx.x; idx < HW; idx += 256) plane[idx] = p[idx];
    float f1[5], f2[5], f4[9], f5[7], f6[7];
#pragma unroll
    for (int j = 0; j < 5; j++) { f1[j] = w1[c * 5 + j]; f2[j] = w2[c * 5 + j]; }
#pragma unroll
    for (int j = 0; j < 9; j++) f4[j] = w4[c * 9 + j];
#pragma unroll
    for (int j = 0; j < 7; j++) { f5[j] = w5[c * 7 + j]; f6[j] = w6[c * 7 + j]; }
    float f3 = w3[c];
    float bias = b1[c] + b2[c] + b3[c] + b4[c] + b5[c] + b6[c];
    __syncthreads();
    for (int idx = threadIdx.x; idx < HW; idx += 256) {
        int i = idx >> 7, w = idx & 127;
        float acc = bias + f3 * plane[idx];
#pragma unroll
        for (int j = 0; j < 5; j++) { int ww = w + j - 2; if ((unsigned)ww < Ww) acc += f1[j] * plane[i * Ww + ww]; }
#pragma unroll
        for (int j = 0; j < 5; j++) { int ii = i + j - 2; if ((unsigned)ii < Hh) acc += f2[j] * plane[ii * Ww + w]; }
#pragma unroll
        for (int pq = 0; pq < 9; pq++) {
            int ii = i + pq / 3 - 1, ww = w + pq % 3 - 1;
            if ((unsigned)ii < Hh && (unsigned)ww < Ww) acc += f4[pq] * plane[ii * Ww + ww];
        }
#pragma unroll
        for (int j = 0; j < 7; j++) { int ww = w + j - 3; if ((unsigned)ww < Ww) acc += f5[j] * plane[i * Ww + ww]; }
#pragma unroll
        for (int j = 0; j < 7; j++) { int ii = i + j - 3; if ((unsigned)ii < Hh) acc += f6[j] * plane[ii * Ww + w]; }
        out[(size_t)bc * HW + idx] = acc;
    }
}

// ---------------- rearrange out1 -> hwc + whc + hwc-rownorm ------------------
__global__ __launch_bounds__(256) void rearrange_out1(const float* __restrict__ src,
                                                      float* __restrict__ hwc,
                                                      float* __restrict__ whc,
                                                      float* __restrict__ nrm) {
    int r = blockIdx.x;
    int i = r & 127, bh = r >> 7;
    int b = bh >> 3, hd = bh & 7;
    __shared__ float tile[16][129];
    __shared__ float red[256];
    float sq = 0.f;
    for (int idx = threadIdx.x; idx < 2048; idx += 256) {
        int c = idx >> 7, w = idx & 127;
        float v = src[((size_t)(b * Cc + hd * 16 + c) * Hh + i) * Ww + w];
        tile[c][w] = v;
        sq += v * v;
    }
    red[threadIdx.x] = sq;
    __syncthreads();
    for (int o = 128; o; o >>= 1) { if (threadIdx.x < o) red[threadIdx.x] += red[threadIdx.x + o]; __syncthreads(); }
    if (threadIdx.x == 0) nrm[bh * 128 + i] = fmaxf(sqrtf(red[0]), 1e-12f);
    float* dh = hwc + ((size_t)bh * Hh + i) * DD;
    float* dw = whc + (size_t)bh * Ww * DD + i * 16;
    for (int idx = threadIdx.x; idx < 2048; idx += 256) {
        int w = idx >> 4, c = idx & 15;
        float v = tile[c][w];
        dh[idx] = v;
        dw[(size_t)w * DD + c] = v;
    }
}

__global__ __launch_bounds__(256) void whc_kernel(const float* __restrict__ src, float* __restrict__ dst) {
    int r = blockIdx.x;
    int i = r & 127, bh = r >> 7;
    int b = bh >> 3, hd = bh & 7;
    __shared__ float tile[16][129];
    for (int idx = threadIdx.x; idx < 2048; idx += 256) {
        int c = idx >> 7, w = idx & 127;
        tile[c][w] = src[((size_t)(b * Cc + hd * 16 + c) * Hh + i) * Ww + w];
    }
    __syncthreads();
    float* d = dst + (size_t)bh * Ww * DD + i * 16;
    for (int idx = threadIdx.x; idx < 2048; idx += 256) {
        int w = idx >> 4, c = idx & 15;
        d[(size_t)w * DD + c] = tile[c][w];
    }
}

// two buffers' row norms in one launch
__global__ __launch_bounds__(256) void rownorm2(const float* __restrict__ bA,
                                                const float* __restrict__ bB,
                                                float* __restrict__ nA,
                                                float* __restrict__ nB) {
    int r = blockIdx.x, tid = threadIdx.x;
    const float* p;
    float* n;
    int row;
    if (r < BH * Ww) { p = bA; n = nA; row = r; }
    else { p = bB; n = nB; row = r - BH * Ww; }
    p += (size_t)row * DD;
    float sq = 0.f;
    for (int idx = tid; idx < DD; idx += 256) { float v = p[idx]; sq += v * v; }
    __shared__ float rq[256];
    rq[tid] = sq;
    __syncthreads();
    for (int o = 128; o; o >>= 1) { if (tid < o) rq[tid] += rq[tid + o]; __syncthreads(); }
    if (tid == 0) n[row] = fmaxf(sqrtf(rq[0]), 1e-12f);
}

// ---------------- QK^T + softmax (tf32) --------------------------------------
__global__ __launch_bounds__(256) void qk_tf32(const float* __restrict__ Q,
                                               const float* __restrict__ K,
                                               const float* __restrict__ qn,
                                               const float* __restrict__ kn,
                                               float* __restrict__ A) {
    __shared__ float Lsm[64][132];
    unsigned* sb = (unsigned*)Lsm;
    unsigned (*Qs)[36] = (unsigned(*)[36])sb;
    unsigned (*Ks)[36] = (unsigned(*)[36])(sb + 64 * 36);
    int bh = blockIdx.x;
    int m0 = blockIdx.y * 64;
    const float* q = Q + (size_t)(bh * 128 + m0) * DD;
    const float* k = K + (size_t)bh * 128 * DD;
    int tid = threadIdx.x, lane = tid & 31, wid = tid >> 5;
    int gid = lane >> 2, tig = lane & 3;
    int m_base = (wid >> 2) * 32, n_base = (wid & 3) * 32;
    float C[2][4][4];
#pragma unroll
    for (int a = 0; a < 2; a++)
#pragma unroll
        for (int c = 0; c < 4; c++)
#pragma unroll
            for (int d = 0; d < 4; d++) C[a][c][d] = 0.f;
    uint4 pq[2], pk[4];
#pragma unroll
    for (int r = 0; r < 2; r++) {
        int e = (tid + r * 256) * 4;
        int m = e >> 5, kk = e & 31;
        pq[r] = cvt4(*(const float4*)&q[(size_t)m * DD + kk]);
    }
#pragma unroll
    for (int r = 0; r < 4; r++) {
        int e = (tid + r * 256) * 4;
        int n = e >> 5, kk = e & 31;
        pk[r] = cvt4(*(const float4*)&k[(size_t)n * DD + kk]);
    }
    for (int ch = 0; ch < 64; ch++) {
#pragma unroll
        for (int r = 0; r < 2; r++) {
            int e = (tid + r * 256) * 4;
            int m = e >> 5, kk = e & 31;
            *(uint4*)&Qs[m][kk] = pq[r];
        }
#pragma unroll
        for (int r = 0; r < 4; r++) {
            int e = (tid + r * 256) * 4;
            int n = e >> 5, kk = e & 31;
            *(uint4*)&Ks[n][kk] = pk[r];
        }
        __syncthreads();
        if (ch + 1 < 64) {
            int k0 = (ch + 1) * 32;
#pragma unroll
            for (int r = 0; r < 2; r++) {
                int e = (tid + r * 256) * 4;
                int m = e >> 5, kk = e & 31;
                pq[r] = cvt4(*(const float4*)&q[(size_t)m * DD + k0 + kk]);
            }
#pragma unroll
            for (int r = 0; r < 4; r++) {
                int e = (tid + r * 256) * 4;
                int n = e >> 5, kk = e & 31;
                pk[r] = cvt4(*(const float4*)&k[(size_t)n * DD + k0 + kk]);
            }
        }
#pragma unroll
        for (int ks = 0; ks < 4; ks++) {
            unsigned b0[4], b1[4];
#pragma unroll
            for (int nt = 0; nt < 4; nt++) {
                b0[nt] = Ks[n_base + nt * 8 + gid][ks * 8 + tig];
                b1[nt] = Ks[n_base + nt * 8 + gid][ks * 8 + tig + 4];
            }
#pragma unroll
            for (int mt = 0; mt < 2; mt++) {
                int m = m_base + mt * 16;
                unsigned a0 = Qs[m + gid][ks * 8 + tig];
                unsigned a1 = Qs[m + 8 + gid][ks * 8 + tig];
                unsigned a2 = Qs[m + gid][ks * 8 + tig + 4];
                unsigned a3 = Qs[m + 8 + gid][ks * 8 + tig + 4];
#pragma unroll
                for (int nt = 0; nt < 4; nt++) mma_tf32(C[mt][nt], a0, a1, a2, a3, b0[nt], b1[nt]);
            }
        }
        __syncthreads();
    }
#pragma unroll
    for (int mt = 0; mt < 2; mt++)
#pragma unroll
        for (int half = 0; half < 2; half++) {
            int m = m_base + mt * 16 + gid + half * 8;
            float invq = 1.f / qn[bh * 128 + m0 + m];
#pragma unroll
            for (int nt = 0; nt < 4; nt++) {
                int n = n_base + nt * 8 + 2 * tig;
                Lsm[m][n]     = C[mt][nt][half * 2 + 0] * invq / kn[bh * 128 + n];
                Lsm[m][n + 1] = C[mt][nt][half * 2 + 1] * invq / kn[bh * 128 + n + 1];
            }
        }
    __syncthreads();
    {
        int row = wid * 8;
        for (int rr = 0; rr < 8; rr++, row++) {
            float v[4];
#pragma unroll
            for (int j = 0; j < 4; j++) v[j] = Lsm[row][lane + j * 32];
            float mx = fmaxf(fmaxf(v[0], v[1]), fmaxf(v[2], v[3]));
            for (int o = 16; o; o >>= 1) mx = fmaxf(mx, __shfl_xor_sync(0xffffffffu, mx, o));
            float sum = 0.f;
#pragma unroll
            for (int j = 0; j < 4; j++) { v[j] = __expf(v[j] - mx); sum += v[j]; }
            for (int o = 16; o; o >>= 1) sum += __shfl_xor_sync(0xffffffffu, sum, o);
            float inv = 1.f / sum;
            float* ap = A + ((size_t)(bh * 128 + m0 + row)) * 128;
#pragma unroll
            for (int j = 0; j < 4; j++) ap[lane + j * 32] = v[j] * inv;
        }
    }
}

// ---------------- A @ V + normalized Q ---------------------------------------
__global__ __launch_bounds__(256) void av_tf32(const float* __restrict__ A,
                                               const float* __restrict__ V,
                                               const float* __restrict__ Q,
                                               const float* __restrict__ qn,
                                               float* __restrict__ out) {
    __shared__ unsigned Ap[128][36];
    __shared__ unsigned Vs[32][136];
    int bh = blockIdx.x;
    int n0 = blockIdx.y * 128;
    const float* a = A + (size_t)bh * 128 * 128;
    const float* v = V + (size_t)bh * 128 * DD + n0;
    int tid = threadIdx.x, lane = tid & 31, wid = tid >> 5;
    int gid = lane >> 2, tig = lane & 3;
    int m_base = (wid >> 2) * 64, n_base = (wid & 3) * 32;
    float C[4][4][4];
#pragma unroll
    for (int x = 0; x < 4; x++)
#pragma unroll
        for (int y = 0; y < 4; y++)
#pragma unroll
            for (int d = 0; d < 4; d++) C[x][y][d] = 0.f;
    uint4 pa[4], pv[4];
#pragma unroll
    for (int r = 0; r < 4; r++) {
        int e = (tid + r * 256) * 4;
        int m = e >> 5, kk = e & 31;
        pa[r] = cvt4(*(const float4*)&a[(size_t)m * 128 + kk]);
    }
#pragma unroll
    for (int r = 0; r < 4; r++) {
        int e = (tid + r * 256) * 4;
        int kk = e >> 7, n = e & 127;
        pv[r] = cvt4(*(const float4*)&v[(size_t)kk * DD + n]);
    }
    for (int ch = 0; ch < 4; ch++) {
#pragma unroll
        for (int r = 0; r < 4; r++) {
            int e = (tid + r * 256) * 4;
            int m = e >> 5, kk = e & 31;
            *(uint4*)&Ap[m][kk] = pa[r];
        }
#pragma unroll
        for (int r = 0; r < 4; r++) {
            int e = (tid + r * 256) * 4;
            int kk = e >> 7, n = e & 127;
            *(uint4*)&Vs[kk][n] = pv[r];
        }
        __syncthreads();
        if (ch + 1 < 4) {
            int k0 = (ch + 1) * 32;
#pragma unroll
            for (int r = 0; r < 4; r++) {
                int e = (tid + r * 256) * 4;
                int m = e >> 5, kk = e & 31;
                pa[r] = cvt4(*(const float4*)&a[(size_t)m * 128 + k0 + kk]);
            }
#pragma unroll
            for (int r = 0; r < 4; r++) {
                int e = (tid + r * 256) * 4;
                int kk = e >> 7, n = e & 127;
                pv[r] = cvt4(*(const float4*)&v[(size_t)(k0 + kk) * DD + n]);
            }
        }
#pragma unroll
        for (int ks = 0; ks < 4; ks++) {
            unsigned b0[4], b1[4];
#pragma unroll
            for (int nt = 0; nt < 4; nt++) {
                b0[nt] = Vs[ks * 8 + tig][n_base + nt * 8 + gid];
                b1[nt] = Vs[ks * 8 + tig + 4][n_base + nt * 8 + gid];
            }
#pragma unroll
            for (int mt = 0; mt < 4; mt++) {
                int m = m_base + mt * 16;
                unsigned a0 = Ap[m + gid][ks * 8 + tig];
                unsigned a1 = Ap[m + 8 + gid][ks * 8 + tig];
                unsigned a2 = Ap[m + gid][ks * 8 + tig + 4];
                unsigned a3 = Ap[m + 8 + gid][ks * 8 + tig + 4];
#pragma unroll
                for (int nt = 0; nt < 4; nt++) mma_tf32(C[mt][nt], a0, a1, a2, a3, b0[nt], b1[nt]);
            }
        }
        __syncthreads();
    }
#pragma unroll
    for (int mt = 0; mt < 4; mt++)
#pragma unroll
        for (int half = 0; half < 2; half++) {
            int m = m_base + mt * 16 + gid + half * 8;
            float invq = 1.f / qn[bh * 128 + m];
            const float* qp = Q + ((size_t)(bh * 128 + m)) * DD + n0;
            float* op = out + ((size_t)(bh * 128 + m)) * DD + n0;
#pragma unroll
            for (int nt = 0; nt < 4; nt++) {
                int n = n_base + nt * 8 + 2 * tig;
                float2 t;
                t.x = C[mt][nt][half * 2 + 0] + qp[n] * invq;
                t.y = C[mt][nt][half * 2 + 1] + qp[n + 1] * invq;
                *(float2*)&op[n] = t;
            }
        }
}

// ---------------- merge o3+o4 back to NCHW -----------------------------------
__global__ __launch_bounds__(256) void merge_kernel(const float* __restrict__ o3,
                                                    const float* __restrict__ o4,
                                                    float* __restrict__ out) {
    int r = blockIdx.x;
    int i = r & 127, bh = r >> 7;
    int b = bh >> 3, hd = bh & 7;
    __shared__ float t3[128][17];
    __shared__ float t4[128][17];
    const float* p3 = o3 + ((size_t)bh * Hh + i) * DD;
    const float* p4 = o4 + (size_t)bh * Ww * DD + i * 16;
    for (int idx = threadIdx.x; idx < 2048; idx += 256) {
        int w = idx >> 4, c = idx & 15;
        t3[w][c] = p3[idx];
        t4[w][c] = p4[(size_t)w * DD + c];
    }
    __syncthreads();
    for (int idx = threadIdx.x; idx < 2048; idx += 256) {
        int c = idx >> 7, w = idx & 127;
        out[((size_t)(b * Cc + hd * 16 + c) * Hh + i) * Ww + w] = t3[w][c] + t4[w][c];
    }
}

// ---------------- launch -----------------------------------------------------
extern "C" void kernel_launch(void* const* d_in, const int* in_sizes, int n_in,
                              void* d_out, int out_size) {
    const float* x    = (const float*)d_in[0];
    const float* ln_w = (const float*)d_in[1];
    const float* ln_b = (const float*)d_in[2];
    const float* wd1  = (const float*)d_in[3];
    const float* gd1  = (const float*)d_in[4];
    const float* bd1  = (const float*)d_in[5];
    const float* wd2  = (const float*)d_in[6];
    const float* gd2  = (const float*)d_in[7];
    const float* bd2  = (const float*)d_in[8];
    const float* wd3  = (const float*)d_in[9];
    const float* gd3  = (const float*)d_in[10];
    const float* bd3  = (const float*)d_in[11];
    const float* w_out1 = (const float*)d_in[12];
    const float* w1 = (const float*)d_in[13]; const float* b1 = (const float*)d_in[14];
    const float* w2 = (const float*)d_in[15]; const float* b2 = (const float*)d_in[16];
    const float* w3 = (const float*)d_in[17]; const float* b3 = (const float*)d_in[18];
    const float* w4 = (const float*)d_in[19]; const float* b4 = (const float*)d_in[20];
    const float* w5 = (const float*)d_in[21]; const float* b5 = (const float*)d_in[22];
    const float* w6 = (const float*)d_in[23]; const float* b6 = (const float*)d_in[24];
    const float* w_out2 = (const float*)d_in[25];
    float* outp = (float*)d_out;

    float *p_x1, *p_y, *p_s, *p_out2, *p_hwc1, *p_whc1, *p_whc2;
    float *p_A1, *p_A2, *p_n1, *p_n2, *p_n3;
    float *p_wp1, *p_wp2, *p_wp3, *p_wpo1, *p_wpo2;
    cudaGetSymbolAddress((void**)&p_x1, g_x1);
    cudaGetSymbolAddress((void**)&p_y, g_y);
    cudaGetSymbolAddress((void**)&p_s, g_s);
    cudaGetSymbolAddress((void**)&p_out2, g_out2);
    cudaGetSymbolAddress((void**)&p_hwc1, g_hwc1);
    cudaGetSymbolAddress((void**)&p_whc1, g_whc1);
    cudaGetSymbolAddress((void**)&p_whc2, g_whc2);
    cudaGetSymbolAddress((void**)&p_A1, g_A1);
    cudaGetSymbolAddress((void**)&p_A2, g_A2);
    cudaGetSymbolAddress((void**)&p_n1, g_n_hwc1);
    cudaGetSymbolAddress((void**)&p_n2, g_n_whc1);
    cudaGetSymbolAddress((void**)&p_n3, g_n_whc2);
    cudaGetSymbolAddress((void**)&p_wp1, g_wp1);
    cudaGetSymbolAddress((void**)&p_wp2, g_wp2);
    cudaGetSymbolAddress((void**)&p_wp3, g_wp3);
    cudaGetSymbolAddress((void**)&p_wpo1, g_wpo1);
    cudaGetSymbolAddress((void**)&p_wpo2, g_wpo2);

    cudaFuncSetAttribute(dw_kernel, cudaFuncAttributeMaxDynamicSharedMemorySize, HW * 4);

    // #1: all weight packs in one launch
    pack_all<<<1344, 256>>>(wd1, wd2, wd3, w_out1, w_out2);
    // #2: x1 = LayerNorm(x)
    ln_kernel<<<Bb * Hh, 128>>>(x, ln_w, ln_b, p_x1);
    // #3-#5: the three dense convs  (#5/#6 land in the ncu capture window)
    conv_tf32<<<Bb * Hh, 256>>>(x, p_wp1, nullptr, p_y, 1, 1);       // y1
    conv_tf32<<<Bb * Hh, 256>>>(x, p_wp2, nullptr, p_hwc1, 9, 6);    // y2
    conv_tf32<<<Bb * Hh, 256>>>(x, p_wp3, nullptr, p_whc1, 9, 12);   // y3
    // #6: depthwise branch (att -> p_whc2, free until whc(out2))
    dw_kernel<<<Bb * Cc, 256, HW * 4>>>(p_x1, w1, b1, w2, b2, w3, b3, w4, b4, w5, b5, w6, b6, p_whc2);
    // BN stats + fused bn-relu-sum
    chan_stats3<<<3 * Cc, 256>>>(p_y, p_hwc1, p_whc1);
    bnrelu3<<<NELEM / 256, 256>>>(p_y, p_hwc1, p_whc1, gd1, bd1, gd2, bd2, gd3, bd3, p_s);
    // out2 = conv1x1(sum, w_out1) + x
    conv_tf32<<<Bb * Hh, 256>>>(p_s, p_wpo1, x, p_out2, 1, 1);
    // out1 = conv1x1(att, w_out2) -> p_x1 (x1 consumed by dw)
    conv_tf32<<<Bb * Hh, 256>>>(p_whc2, p_wpo2, nullptr, p_x1, 1, 1);

    // rearranges + norms
    rearrange_out1<<<BH * Hh, 256>>>(p_x1, p_hwc1, p_whc1, p_n1);
    whc_kernel<<<BH * Hh, 256>>>(p_out2, p_whc2);
    rownorm2<<<2 * BH * Ww, 256>>>(p_whc1, p_whc2, p_n2, p_n3);

    // attention
    qk_tf32<<<dim3(BH, 2), 256>>>(p_whc2, p_hwc1, p_n3, p_n1, p_A1);
    qk_tf32<<<dim3(BH, 2), 256>>>(p_whc1, p_whc2, p_n2, p_n3, p_A2);
    av_tf32<<<dim3(BH, 16), 256>>>(p_A1, p_hwc1, p_whc2, p_n3, p_s);   // out3
    av_tf32<<<dim3(BH, 16), 256>>>(p_A2, p_whc2, p_whc1, p_n2, p_y);   // out4

    // merge + final conv
    merge_kernel<<<BH * Hh, 256>>>(p_s, p_y, p_out2);
    conv_tf32<<<Bb * Hh, 256>>>(p_out2, p_wpo2, x, outp, 1, 1);
}

// round 5
// speedup vs baseline: 1.8301x; 1.2345x over previous
#include <cuda_runtime.h>

#define Bb 8
#define Cc 128
#define Hh 128
#define Ww 128
#define HW 16384
#define NELEM (Bb*Cc*HW)
#define DD 2048
#define BH 64

// ---------------- scratch ----------------------------------------------------
__device__ float g_x1[NELEM];     // LN out; later out1
__device__ float g_y[NELEM];      // y1; later out4
__device__ float g_s[NELEM];      // x_tf32 first; then bn-relu sum; later out3
__device__ float g_out2[NELEM];   // out2; later merged o3+o4
__device__ float g_hwc1[NELEM];   // y2; then hwc(out1)
__device__ float g_whc1[NELEM];   // y3; then whc(out1)
__device__ float g_whc2[NELEM];   // att; then whc(out2)
__device__ float g_A1[BH*Hh*Ww];
__device__ float g_A2[BH*Hh*Ww];
__device__ float g_n_hwc1[BH*Hh];
__device__ float g_n_whc1[BH*Ww];
__device__ float g_n_whc2[BH*Ww];
__device__ float g_stats[6*Cc];
__device__ float g_wp1[Cc*Cc];
__device__ float g_wp2[9*Cc*Cc];
__device__ float g_wp3[9*Cc*Cc];
__device__ float g_wpo1[Cc*Cc];
__device__ float g_wpo2[Cc*Cc];

// ---------------- tf32 helpers ----------------------------------------------
__device__ __forceinline__ unsigned cvt1(float f) {
    unsigned u; asm("cvt.rna.tf32.f32 %0, %1;" : "=r"(u) : "f"(f)); return u;
}
__device__ __forceinline__ uint4 cvt4(float4 f) {
    uint4 u;
    asm("cvt.rna.tf32.f32 %0, %1;" : "=r"(u.x) : "f"(f.x));
    asm("cvt.rna.tf32.f32 %0, %1;" : "=r"(u.y) : "f"(f.y));
    asm("cvt.rna.tf32.f32 %0, %1;" : "=r"(u.z) : "f"(f.z));
    asm("cvt.rna.tf32.f32 %0, %1;" : "=r"(u.w) : "f"(f.w));
    return u;
}
__device__ __forceinline__ void mma_tf32(float* c, unsigned a0, unsigned a1,
                                         unsigned a2, unsigned a3,
                                         unsigned b0, unsigned b1) {
    asm volatile("mma.sync.aligned.m16n8k8.row.col.f32.tf32.tf32.f32 "
                 "{%0,%1,%2,%3}, {%4,%5,%6,%7}, {%8,%9}, {%0,%1,%2,%3};"
                 : "+f"(c[0]), "+f"(c[1]), "+f"(c[2]), "+f"(c[3])
                 : "r"(a0), "r"(a1), "r"(a2), "r"(a3), "r"(b0), "r"(b1));
}
__device__ __forceinline__ void cpa4(unsigned dst, const void* src, int sz) {
    asm volatile("cp.async.ca.shared.global [%0], [%1], 4, %2;" :: "r"(dst), "l"(src), "r"(sz));
}
__device__ __forceinline__ void cpa16(unsigned dst, const void* src) {
    asm volatile("cp.async.cg.shared.global [%0], [%1], 16;" :: "r"(dst), "l"(src));
}
__device__ __forceinline__ void cpa_commit() { asm volatile("cp.async.commit_group;"); }
__device__ __forceinline__ void cpa_wait0() { asm volatile("cp.async.wait_group 0;"); }

// ---------------- single-launch weight pack ----------------------------------
__device__ __forceinline__ void pack_one(const float* __restrict__ w,
                                         float* __restrict__ wp, int taps, int idx) {
    int co = idx / (Cc * taps);
    int rem = idx % (Cc * taps);
    int ci = rem / taps;
    int tap = rem % taps;
    wp[(tap * Cc + ci) * Cc + co] = __uint_as_float(cvt1(w[idx]));
}
__global__ void pack_all(const float* __restrict__ wd1, const float* __restrict__ wd2,
                         const float* __restrict__ wd3, const float* __restrict__ wo1,
                         const float* __restrict__ wo2) {
    int idx = blockIdx.x * 256 + threadIdx.x;
    if (idx < 16384)            pack_one(wd1, g_wp1, 1, idx);
    else if (idx < 163840)      pack_one(wd2, g_wp2, 9, idx - 16384);
    else if (idx < 311296)      pack_one(wd3, g_wp3, 9, idx - 163840);
    else if (idx < 327680)      pack_one(wo1, g_wpo1, 1, idx - 311296);
    else if (idx < 344064)      pack_one(wo2, g_wpo2, 1, idx - 327680);
}

// ---------------- round x to tf32 once ---------------------------------------
__global__ __launch_bounds__(256) void round_x(const float* __restrict__ x, float* __restrict__ o) {
    int idx = blockIdx.x * 256 + threadIdx.x;
    float4 v = *(const float4*)&x[idx * 4];
    uint4 u = cvt4(v);
    *(uint4*)&o[idx * 4] = u;
}

// ---------------- LayerNorm over channels ------------------------------------
__global__ __launch_bounds__(128) void ln_kernel(const float* __restrict__ x,
                                                 const float* __restrict__ lw,
                                                 const float* __restrict__ lb,
                                                 float* __restrict__ o) {
    int bi = blockIdx.x;
    int b = bi >> 7, i = bi & 127;
    int w = threadIdx.x;
    const float* p = x + (size_t)b * Cc * HW + i * Ww + w;
    float s = 0.f, sq = 0.f;
    for (int c = 0; c < Cc; c++) { float v = p[(size_t)c * HW]; s += v; sq += v * v; }
    float mu = s * (1.f / Cc);
    float var = sq * (1.f / Cc) - mu * mu;
    float r = rsqrtf(var + 1e-5f);
    float* op = o + (size_t)b * Cc * HW + i * Ww + w;
    for (int c = 0; c < Cc; c++) {
        float v = p[(size_t)c * HW];
        op[(size_t)c * HW] = (v - mu) * r * lw[c] + lb[c];
    }
}

// ---------------- conv: templated, cp.async 2-stage, pre-rounded input -------
template<int TAPS, int DIL>
__global__ __launch_bounds__(256) void conv_tf32(const float* __restrict__ in,
                                                 const float* __restrict__ wp,
                                                 const float* __restrict__ resid,
                                                 float* __restrict__ out) {
    extern __shared__ unsigned smem[];
    // layout: A stage0, A stage1, B stage0, B stage1; each 32*136
    unsigned (*Asm)[136] = (unsigned(*)[136])smem;
    unsigned (*Bsm)[136] = (unsigned(*)[136])(smem + 2 * 32 * 136);
    int bi = blockIdx.x;
    int b = bi >> 7, i = bi & 127;
    int tid = threadIdx.x, lane = tid & 31, wid = tid >> 5;
    int gid = lane >> 2, tig = lane & 3;
    int m_base = (wid >> 2) * 64, n_base = (wid & 3) * 32;
    float C[4][4][4];
#pragma unroll
    for (int a = 0; a < 4; a++)
#pragma unroll
        for (int c = 0; c < 4; c++)
#pragma unroll
            for (int d = 0; d < 4; d++) C[a][c][d] = 0.f;
    const int nch = TAPS * 4;
    const float* inb = in + (size_t)b * Cc * HW;
    // per-thread constants for B loader
    const int w = tid & 127;          // output column this thread always loads
    const int kk0 = tid >> 7;         // 0 or 1; kk = kk0 + 2r
    // per-thread constants for A loader (16B units)
    // unit u = tid + 256r (r<4): kka = u>>5, m4 = (u&31)*4

    auto issueA = [&](int ch, int st) {
        const float* wpB = wp + (size_t)ch * 32 * 128;
#pragma unroll
        for (int r = 0; r < 4; r++) {
            int u = tid + r * 256;
            int kka = u >> 5, m4 = (u & 31) * 4;
            unsigned dst = (unsigned)__cvta_generic_to_shared(&Asm[st * 32][0]) +
                           (unsigned)((kka * 136 + m4) * 4);
            cpa16(dst, wpB + kka * 128 + m4);
        }
    };
    auto issueB = [&](int ch, int st) {
        int tap = (TAPS == 9) ? (ch >> 2) : 0;
        int ciBase = (TAPS == 9) ? ((ch & 3) * 32) : (ch * 32);
        int dy = 0, dx = 0;
        if (TAPS == 9) { dy = (tap / 3 - 1) * DIL; dx = (tap % 3 - 1) * DIL; }
        int ii = i + dy, ww = w + dx;
        int ok = ((unsigned)ii < 128u && (unsigned)ww < 128u) ? 4 : 0;
        const float* src = inb + (size_t)(ciBase + kk0) * HW + ii * 128 + ww;
        unsigned dstBase = (unsigned)__cvta_generic_to_shared(&Bsm[st * 32][0]) +
                           (unsigned)((kk0 * 136 + w) * 4);
#pragma unroll
        for (int r = 0; r < 16; r++) {
            cpa4(dstBase + (unsigned)(r * 2 * 136 * 4), src + (size_t)r * 2 * HW, ok);
        }
    };

    issueA(0, 0); issueB(0, 0); cpa_commit();

    for (int ch = 0; ch < nch; ch++) {
        cpa_wait0();
        __syncthreads();
        if (ch + 1 < nch) { issueA(ch + 1, (ch + 1) & 1); issueB(ch + 1, (ch + 1) & 1); cpa_commit(); }
        unsigned (*As)[136] = &Asm[(ch & 1) * 32];
        unsigned (*Bs)[136] = &Bsm[(ch & 1) * 32];
#pragma unroll
        for (int ks = 0; ks < 4; ks++) {
            unsigned b0[4], b1[4];
#pragma unroll
            for (int nt = 0; nt < 4; nt++) {
                b0[nt] = Bs[ks * 8 + tig][n_base + nt * 8 + gid];
                b1[nt] = Bs[ks * 8 + tig + 4][n_base + nt * 8 + gid];
            }
#pragma unroll
            for (int mt = 0; mt < 4; mt++) {
                int m = m_base + mt * 16;
                unsigned a0 = As[ks * 8 + tig][m + gid];
                unsigned a1 = As[ks * 8 + tig][m + 8 + gid];
                unsigned a2 = As[ks * 8 + tig + 4][m + gid];
                unsigned a3 = As[ks * 8 + tig + 4][m + 8 + gid];
#pragma unroll
                for (int nt = 0; nt < 4; nt++) mma_tf32(C[mt][nt], a0, a1, a2, a3, b0[nt], b1[nt]);
            }
        }
        __syncthreads();
    }
#pragma unroll
    for (int mt = 0; mt < 4; mt++)
#pragma unroll
        for (int half = 0; half < 2; half++) {
            int m = m_base + mt * 16 + gid + half * 8;
            size_t base = ((size_t)(b * 128 + m) * 128 + i) * 128;
#pragma unroll
            for (int nt = 0; nt < 4; nt++) {
                int n = n_base + nt * 8 + 2 * tig;
                float v0 = C[mt][nt][half * 2 + 0];
                float v1 = C[mt][nt][half * 2 + 1];
                if (resid) { v0 += resid[base + n]; v1 += resid[base + n + 1]; }
                float2 t = {v0, v1};
                *(float2*)&out[base + n] = t;
            }
        }
}

// ---------------- per-channel batch stats for three tensors ------------------
__global__ __launch_bounds__(256) void chan_stats3(const float* __restrict__ y1,
                                                   const float* __restrict__ y2,
                                                   const float* __restrict__ y3) {
    int bx = blockIdx.x;
    int which = bx >> 7, c = bx & 127;
    const float* y = which == 0 ? y1 : (which == 1 ? y2 : y3);
    int tid = threadIdx.x;
    float s = 0.f, sq = 0.f;
    for (int b = 0; b < Bb; b++) {
        const float* p = y + (size_t)(b * Cc + c) * HW;
        for (int idx = tid; idx < HW; idx += 256) { float v = p[idx]; s += v; sq += v * v; }
    }
    __shared__ float rs[256], rq[256];
    rs[tid] = s; rq[tid] = sq;
    __syncthreads();
    for (int o = 128; o; o >>= 1) {
        if (tid < o) { rs[tid] += rs[tid + o]; rq[tid] += rq[tid + o]; }
        __syncthreads();
    }
    if (tid == 0) {
        float inv = 1.f / (float)(Bb * HW);
        float m = rs[0] * inv;
        float var = rq[0] * inv - m * m;
        g_stats[which * 256 + c] = m;
        g_stats[which * 256 + 128 + c] = rsqrtf(var + 1e-5f);
    }
}

__global__ __launch_bounds__(256) void bnrelu3(const float* __restrict__ y1,
                                               const float* __restrict__ y2,
                                               const float* __restrict__ y3,
                                               const float* __restrict__ g1, const float* __restrict__ b1,
                                               const float* __restrict__ g2, const float* __restrict__ b2,
                                               const float* __restrict__ g3, const float* __restrict__ b3,
                                               float* __restrict__ s) {
    int idx = blockIdx.x * 256 + threadIdx.x;
    int c = (idx >> 14) & 127;
    float v1 = fmaxf((y1[idx] - g_stats[c]) * g_stats[128 + c] * g1[c] + b1[c], 0.f);
    float v2 = fmaxf((y2[idx] - g_stats[256 + c]) * g_stats[256 + 128 + c] * g2[c] + b2[c], 0.f);
    float v3 = fmaxf((y3[idx] - g_stats[512 + c]) * g_stats[512 + 128 + c] * g3[c] + b3[c], 0.f);
    s[idx] = __uint_as_float(cvt1(v1 + v2 + v3));   // pre-round for downstream GEMM
}

// ---------------- six depthwise convs fused (output pre-rounded) -------------
__global__ __launch_bounds__(256) void dw_kernel(const float* __restrict__ x1,
    const float* __restrict__ w1, const float* __restrict__ b1,
    const float* __restrict__ w2, const float* __restrict__ b2,
    const float* __restrict__ w3, const float* __restrict__ b3,
    const float* __restrict__ w4, const float* __restrict__ b4,
    const float* __restrict__ w5, const float* __restrict__ b5,
    const float* __restrict__ w6, const float* __restrict__ b6,
    float* __restrict__ out) {
    extern __shared__ float plane[];
    int bc = blockIdx.x;
    int c = bc & 127;
    const float* p = x1 + (size_t)bc * HW;
    for (int idx = threadIdx.x; idx < HW; idx += 256) plane[idx] = p[idx];
    float f1[5], f2[5], f4[9], f5[7], f6[7];
#pragma unroll
    for (int j = 0; j < 5; j++) { f1[j] = w1[c * 5 + j]; f2[j] = w2[c * 5 + j]; }
#pragma unroll
    for (int j = 0; j < 9; j++) f4[j] = w4[c * 9 + j];
#pragma unroll
    for (int j = 0; j < 7; j++) { f5[j] = w5[c * 7 + j]; f6[j] = w6[c * 7 + j]; }
    float f3 = w3[c];
    float bias = b1[c] + b2[c] + b3[c] + b4[c] + b5[c] + b6[c];
    __syncthreads();
    for (int idx = threadIdx.x; idx < HW; idx += 256) {
        int i = idx >> 7, w = idx & 127;
        float acc = bias + f3 * plane[idx];
#pragma unroll
        for (int j = 0; j < 5; j++) { int ww = w + j - 2; if ((unsigned)ww < Ww) acc += f1[j] * plane[i * Ww + ww]; }
#pragma unroll
        for (int j = 0; j < 5; j++) { int ii = i + j - 2; if ((unsigned)ii < Hh) acc += f2[j] * plane[ii * Ww + w]; }
#pragma unroll
        for (int pq = 0; pq < 9; pq++) {
            int ii = i + pq / 3 - 1, ww = w + pq % 3 - 1;
            if ((unsigned)ii < Hh && (unsigned)ww < Ww) acc += f4[pq] * plane[ii * Ww + ww];
        }
#pragma unroll
        for (int j = 0; j < 7; j++) { int ww = w + j - 3; if ((unsigned)ww < Ww) acc += f5[j] * plane[i * Ww + ww]; }
#pragma unroll
        for (int j = 0; j < 7; j++) { int ii = i + j - 3; if ((unsigned)ii < Hh) acc += f6[j] * plane[ii * Ww + w]; }
        out[(size_t)bc * HW + idx] = __uint_as_float(cvt1(acc));
    }
}

// ---------------- rearrange out1 -> hwc + whc + hwc-rownorm ------------------
__global__ __launch_bounds__(256) void rearrange_out1(const float* __restrict__ src,
                                                      float* __restrict__ hwc,
                                                      float* __restrict__ whc,
                                                      float* __restrict__ nrm) {
    int r = blockIdx.x;
    int i = r & 127, bh = r >> 7;
    int b = bh >> 3, hd = bh & 7;
    __shared__ float tile[16][129];
    __shared__ float red[256];
    float sq = 0.f;
    for (int idx = threadIdx.x; idx < 2048; idx += 256) {
        int c = idx >> 7, w = idx & 127;
        float v = src[((size_t)(b * Cc + hd * 16 + c) * Hh + i) * Ww + w];
        tile[c][w] = v;
        sq += v * v;
    }
    red[threadIdx.x] = sq;
    __syncthreads();
    for (int o = 128; o; o >>= 1) { if (threadIdx.x < o) red[threadIdx.x] += red[threadIdx.x + o]; __syncthreads(); }
    if (threadIdx.x == 0) nrm[bh * 128 + i] = fmaxf(sqrtf(red[0]), 1e-12f);
    float* dh = hwc + ((size_t)bh * Hh + i) * DD;
    float* dw = whc + (size_t)bh * Ww * DD + i * 16;
    for (int idx = threadIdx.x; idx < 2048; idx += 256) {
        int w = idx >> 4, c = idx & 15;
        float v = tile[c][w];
        dh[idx] = v;
        dw[(size_t)w * DD + c] = v;
    }
}

__global__ __launch_bounds__(256) void whc_kernel(const float* __restrict__ src, float* __restrict__ dst) {
    int r = blockIdx.x;
    int i = r & 127, bh = r >> 7;
    int b = bh >> 3, hd = bh & 7;
    __shared__ float tile[16][129];
    for (int idx = threadIdx.x; idx < 2048; idx += 256) {
        int c = idx >> 7, w = idx & 127;
        tile[c][w] = src[((size_t)(b * Cc + hd * 16 + c) * Hh + i) * Ww + w];
    }
    __syncthreads();
    float* d = dst + (size_t)bh * Ww * DD + i * 16;
    for (int idx = threadIdx.x; idx < 2048; idx += 256) {
        int w = idx >> 4, c = idx & 15;
        d[(size_t)w * DD + c] = tile[c][w];
    }
}

__global__ __launch_bounds__(256) void rownorm2(const float* __restrict__ bA,
                                                const float* __restrict__ bB,
                                                float* __restrict__ nA,
                                                float* __restrict__ nB) {
    int r = blockIdx.x, tid = threadIdx.x;
    const float* p;
    float* n;
    int row;
    if (r < BH * Ww) { p = bA; n = nA; row = r; }
    else { p = bB; n = nB; row = r - BH * Ww; }
    p += (size_t)row * DD;
    float sq = 0.f;
    for (int idx = tid; idx < DD; idx += 256) { float v = p[idx]; sq += v * v; }
    __shared__ float rq[256];
    rq[tid] = sq;
    __syncthreads();
    for (int o = 128; o; o >>= 1) { if (tid < o) rq[tid] += rq[tid + o]; __syncthreads(); }
    if (tid == 0) n[row] = fmaxf(sqrtf(rq[0]), 1e-12f);
}

// ---------------- QK^T + softmax (tf32) --------------------------------------
__global__ __launch_bounds__(256) void qk_tf32(const float* __restrict__ Q,
                                               const float* __restrict__ K,
                                               const float* __restrict__ qn,
                                               const float* __restrict__ kn,
                                               float* __restrict__ A) {
    __shared__ float Lsm[64][132];
    unsigned* sb = (unsigned*)Lsm;
    unsigned (*Qs)[36] = (unsigned(*)[36])sb;
    unsigned (*Ks)[36] = (unsigned(*)[36])(sb + 64 * 36);
    int bh = blockIdx.x;
    int m0 = blockIdx.y * 64;
    const float* q = Q + (size_t)(bh * 128 + m0) * DD;
    const float* k = K + (size_t)bh * 128 * DD;
    int tid = threadIdx.x, lane = tid & 31, wid = tid >> 5;
    int gid = lane >> 2, tig = lane & 3;
    int m_base = (wid >> 2) * 32, n_base = (wid & 3) * 32;
    float C[2][4][4];
#pragma unroll
    for (int a = 0; a < 2; a++)
#pragma unroll
        for (int c = 0; c < 4; c++)
#pragma unroll
            for (int d = 0; d < 4; d++) C[a][c][d] = 0.f;
    uint4 pq[2], pk[4];
#pragma unroll
    for (int r = 0; r < 2; r++) {
        int e = (tid + r * 256) * 4;
        int m = e >> 5, kk = e & 31;
        pq[r] = cvt4(*(const float4*)&q[(size_t)m * DD + kk]);
    }
#pragma unroll
    for (int r = 0; r < 4; r++) {
        int e = (tid + r * 256) * 4;
        int n = e >> 5, kk = e & 31;
        pk[r] = cvt4(*(const float4*)&k[(size_t)n * DD + kk]);
    }
    for (int ch = 0; ch < 64; ch++) {
#pragma unroll
        for (int r = 0; r < 2; r++) {
            int e = (tid + r * 256) * 4;
            int m = e >> 5, kk = e & 31;
            *(uint4*)&Qs[m][kk] = pq[r];
        }
#pragma unroll
        for (int r = 0; r < 4; r++) {
            int e = (tid + r * 256) * 4;
            int n = e >> 5, kk = e & 31;
            *(uint4*)&Ks[n][kk] = pk[r];
        }
        __syncthreads();
        if (ch + 1 < 64) {
            int k0 = (ch + 1) * 32;
#pragma unroll
            for (int r = 0; r < 2; r++) {
                int e = (tid + r * 256) * 4;
                int m = e >> 5, kk = e & 31;
                pq[r] = cvt4(*(const float4*)&q[(size_t)m * DD + k0 + kk]);
            }
#pragma unroll
            for (int r = 0; r < 4; r++) {
                int e = (tid + r * 256) * 4;
                int n = e >> 5, kk = e & 31;
                pk[r] = cvt4(*(const float4*)&k[(size_t)n * DD + k0 + kk]);
            }
        }
#pragma unroll
        for (int ks = 0; ks < 4; ks++) {
            unsigned b0[4], b1[4];
#pragma unroll
            for (int nt = 0; nt < 4; nt++) {
                b0[nt] = Ks[n_base + nt * 8 + gid][ks * 8 + tig];
                b1[nt] = Ks[n_base + nt * 8 + gid][ks * 8 + tig + 4];
            }
#pragma unroll
            for (int mt = 0; mt < 2; mt++) {
                int m = m_base + mt * 16;
                unsigned a0 = Qs[m + gid][ks * 8 + tig];
                unsigned a1 = Qs[m + 8 + gid][ks * 8 + tig];
                unsigned a2 = Qs[m + gid][ks * 8 + tig + 4];
                unsigned a3 = Qs[m + 8 + gid][ks * 8 + tig + 4];
#pragma unroll
                for (int nt = 0; nt < 4; nt++) mma_tf32(C[mt][nt], a0, a1, a2, a3, b0[nt], b1[nt]);
            }
        }
        __syncthreads();
    }
#pragma unroll
    for (int mt = 0; mt < 2; mt++)
#pragma unroll
        for (int half = 0; half < 2; half++) {
            int m = m_base + mt * 16 + gid + half * 8;
            float invq = 1.f / qn[bh * 128 + m0 + m];
#pragma unroll
            for (int nt = 0; nt < 4; nt++) {
                int n = n_base + nt * 8 + 2 * tig;
                Lsm[m][n]     = C[mt][nt][half * 2 + 0] * invq / kn[bh * 128 + n];
                Lsm[m][n + 1] = C[mt][nt][half * 2 + 1] * invq / kn[bh * 128 + n + 1];
            }
        }
    __syncthreads();
    {
        int row = wid * 8;
        for (int rr = 0; rr < 8; rr++, row++) {
            float v[4];
#pragma unroll
            for (int j = 0; j < 4; j++) v[j] = Lsm[row][lane + j * 32];
            float mx = fmaxf(fmaxf(v[0], v[1]), fmaxf(v[2], v[3]));
            for (int o = 16; o; o >>= 1) mx = fmaxf(mx, __shfl_xor_sync(0xffffffffu, mx, o));
            float sum = 0.f;
#pragma unroll
            for (int j = 0; j < 4; j++) { v[j] = __expf(v[j] - mx); sum += v[j]; }
            for (int o = 16; o; o >>= 1) sum += __shfl_xor_sync(0xffffffffu, sum, o);
            float inv = 1.f / sum;
            float* ap = A + ((size_t)(bh * 128 + m0 + row)) * 128;
#pragma unroll
            for (int j = 0; j < 4; j++) ap[lane + j * 32] = v[j] * inv;
        }
    }
}

// ---------------- A @ V + normalized Q ---------------------------------------
__global__ __launch_bounds__(256) void av_tf32(const float* __restrict__ A,
                                               const float* __restrict__ V,
                                               const float* __restrict__ Q,
                                               const float* __restrict__ qn,
                                               float* __restrict__ out) {
    __shared__ unsigned Ap[128][36];
    __shared__ unsigned Vs[32][136];
    int bh = blockIdx.x;
    int n0 = blockIdx.y * 128;
    const float* a = A + (size_t)bh * 128 * 128;
    const float* v = V + (size_t)bh * 128 * DD + n0;
    int tid = threadIdx.x, lane = tid & 31, wid = tid >> 5;
    int gid = lane >> 2, tig = lane & 3;
    int m_base = (wid >> 2) * 64, n_base = (wid & 3) * 32;
    float C[4][4][4];
#pragma unroll
    for (int x = 0; x < 4; x++)
#pragma unroll
        for (int y = 0; y < 4; y++)
#pragma unroll
            for (int d = 0; d < 4; d++) C[x][y][d] = 0.f;
    uint4 pa[4], pv[4];
#pragma unroll
    for (int r = 0; r < 4; r++) {
        int e = (tid + r * 256) * 4;
        int m = e >> 5, kk = e & 31;
        pa[r] = cvt4(*(const float4*)&a[(size_t)m * 128 + kk]);
    }
#pragma unroll
    for (int r = 0; r < 4; r++) {
        int e = (tid + r * 256) * 4;
        int kk = e >> 7, n = e & 127;
        pv[r] = cvt4(*(const float4*)&v[(size_t)kk * DD + n]);
    }
    for (int ch = 0; ch < 4; ch++) {
#pragma unroll
        for (int r = 0; r < 4; r++) {
            int e = (tid + r * 256) * 4;
            int m = e >> 5, kk = e & 31;
            *(uint4*)&Ap[m][kk] = pa[r];
        }
#pragma unroll
        for (int r = 0; r < 4; r++) {
            int e = (tid + r * 256) * 4;
            int kk = e >> 7, n = e & 127;
            *(uint4*)&Vs[kk][n] = pv[r];
        }
        __syncthreads();
        if (ch + 1 < 4) {
            int k0 = (ch + 1) * 32;
#pragma unroll
            for (int r = 0; r < 4; r++) {
                int e = (tid + r * 256) * 4;
                int m = e >> 5, kk = e & 31;
                pa[r] = cvt4(*(const float4*)&a[(size_t)m * 128 + k0 + kk]);
            }
#pragma unroll
            for (int r = 0; r < 4; r++) {
                int e = (tid + r * 256) * 4;
                int kk = e >> 7, n = e & 127;
                pv[r] = cvt4(*(const float4*)&v[(size_t)(k0 + kk) * DD + n]);
            }
        }
#pragma unroll
        for (int ks = 0; ks < 4; ks++) {
            unsigned b0[4], b1[4];
#pragma unroll
            for (int nt = 0; nt < 4; nt++) {
                b0[nt] = Vs[ks * 8 + tig][n_base + nt * 8 + gid];
                b1[nt] = Vs[ks * 8 + tig + 4][n_base + nt * 8 + gid];
            }
#pragma unroll
            for (int mt = 0; mt < 4; mt++) {
                int m = m_base + mt * 16;
                unsigned a0 = Ap[m + gid][ks * 8 + tig];
                unsigned a1 = Ap[m + 8 + gid][ks * 8 + tig];
                unsigned a2 = Ap[m + gid][ks * 8 + tig + 4];
                unsigned a3 = Ap[m + 8 + gid][ks * 8 + tig + 4];
#pragma unroll
                for (int nt = 0; nt < 4; nt++) mma_tf32(C[mt][nt], a0, a1, a2, a3, b0[nt], b1[nt]);
            }
        }
        __syncthreads();
    }
#pragma unroll
    for (int mt = 0; mt < 4; mt++)
#pragma unroll
        for (int half = 0; half < 2; half++) {
            int m = m_base + mt * 16 + gid + half * 8;
            float invq = 1.f / qn[bh * 128 + m];
            const float* qp = Q + ((size_t)(bh * 128 + m)) * DD + n0;
            float* op = out + ((size_t)(bh * 128 + m)) * DD + n0;
#pragma unroll
            for (int nt = 0; nt < 4; nt++) {
                int n = n_base + nt * 8 + 2 * tig;
                float2 t;
                t.x = C[mt][nt][half * 2 + 0] + qp[n] * invq;
                t.y = C[mt][nt][half * 2 + 1] + qp[n + 1] * invq;
                *(float2*)&op[n] = t;
            }
        }
}

// ---------------- merge o3+o4 back to NCHW (output pre-rounded) --------------
__global__ __launch_bounds__(256) void merge_kernel(const float* __restrict__ o3,
                                                    const float* __restrict__ o4,
                                                    float* __restrict__ out) {
    int r = blockIdx.x;
    int i = r & 127, bh = r >> 7;
    int b = bh >> 3, hd = bh & 7;
    __shared__ float t3[128][17];
    __shared__ float t4[128][17];
    const float* p3 = o3 + ((size_t)bh * Hh + i) * DD;
    const float* p4 = o4 + (size_t)bh * Ww * DD + i * 16;
    for (int idx = threadIdx.x; idx < 2048; idx += 256) {
        int w = idx >> 4, c = idx & 15;
        t3[w][c] = p3[idx];
        t4[w][c] = p4[(size_t)w * DD + c];
    }
    __syncthreads();
    for (int idx = threadIdx.x; idx < 2048; idx += 256) {
        int c = idx >> 7, w = idx & 127;
        out[((size_t)(b * Cc + hd * 16 + c) * Hh + i) * Ww + w] =
            __uint_as_float(cvt1(t3[w][c] + t4[w][c]));
    }
}

// ---------------- launch -----------------------------------------------------
#define SMEM_CONV (4 * 32 * 136 * 4)

extern "C" void kernel_launch(void* const* d_in, const int* in_sizes, int n_in,
                              void* d_out, int out_size) {
    const float* x    = (const float*)d_in[0];
    const float* ln_w = (const float*)d_in[1];
    const float* ln_b = (const float*)d_in[2];
    const float* wd1  = (const float*)d_in[3];
    const float* gd1  = (const float*)d_in[4];
    const float* bd1  = (const float*)d_in[5];
    const float* wd2  = (const float*)d_in[6];
    const float* gd2  = (const float*)d_in[7];
    const float* bd2  = (const float*)d_in[8];
    const float* wd3  = (const float*)d_in[9];
    const float* gd3  = (const float*)d_in[10];
    const float* bd3  = (const float*)d_in[11];
    const float* w_out1 = (const float*)d_in[12];
    const float* w1 = (const float*)d_in[13]; const float* b1 = (const float*)d_in[14];
    const float* w2 = (const float*)d_in[15]; const float* b2 = (const float*)d_in[16];
    const float* w3 = (const float*)d_in[17]; const float* b3 = (const float*)d_in[18];
    const float* w4 = (const float*)d_in[19]; const float* b4 = (const float*)d_in[20];
    const float* w5 = (const float*)d_in[21]; const float* b5 = (const float*)d_in[22];
    const float* w6 = (const float*)d_in[23]; const float* b6 = (const float*)d_in[24];
    const float* w_out2 = (const float*)d_in[25];
    float* outp = (float*)d_out;

    float *p_x1, *p_y, *p_s, *p_out2, *p_hwc1, *p_whc1, *p_whc2;
    float *p_A1, *p_A2, *p_n1, *p_n2, *p_n3;
    float *p_wp1, *p_wp2, *p_wp3, *p_wpo1, *p_wpo2;
    cudaGetSymbolAddress((void**)&p_x1, g_x1);
    cudaGetSymbolAddress((void**)&p_y, g_y);
    cudaGetSymbolAddress((void**)&p_s, g_s);
    cudaGetSymbolAddress((void**)&p_out2, g_out2);
    cudaGetSymbolAddress((void**)&p_hwc1, g_hwc1);
    cudaGetSymbolAddress((void**)&p_whc1, g_whc1);
    cudaGetSymbolAddress((void**)&p_whc2, g_whc2);
    cudaGetSymbolAddress((void**)&p_A1, g_A1);
    cudaGetSymbolAddress((void**)&p_A2, g_A2);
    cudaGetSymbolAddress((void**)&p_n1, g_n_hwc1);
    cudaGetSymbolAddress((void**)&p_n2, g_n_whc1);
    cudaGetSymbolAddress((void**)&p_n3, g_n_whc2);
    cudaGetSymbolAddress((void**)&p_wp1, g_wp1);
    cudaGetSymbolAddress((void**)&p_wp2, g_wp2);
    cudaGetSymbolAddress((void**)&p_wp3, g_wp3);
    cudaGetSymbolAddress((void**)&p_wpo1, g_wpo1);
    cudaGetSymbolAddress((void**)&p_wpo2, g_wpo2);

    cudaFuncSetAttribute(dw_kernel, cudaFuncAttributeMaxDynamicSharedMemorySize, HW * 4);
    cudaFuncSetAttribute(conv_tf32<1, 1>, cudaFuncAttributeMaxDynamicSharedMemorySize, SMEM_CONV);
    cudaFuncSetAttribute(conv_tf32<9, 6>, cudaFuncAttributeMaxDynamicSharedMemorySize, SMEM_CONV);
    cudaFuncSetAttribute(conv_tf32<9, 12>, cudaFuncAttributeMaxDynamicSharedMemorySize, SMEM_CONV);

    // #1 packs, #2 round x, #3 LN
    pack_all<<<1344, 256>>>(wd1, wd2, wd3, w_out1, w_out2);
    round_x<<<NELEM / 1024, 256>>>(x, p_s);             // x_tf32 -> g_s (free until bnrelu3)
    ln_kernel<<<Bb * Hh, 128>>>(x, ln_w, ln_b, p_x1);
    // #4-#6: dense convs on pre-rounded x (dilated ones land in ncu window)
    conv_tf32<9, 6><<<Bb * Hh, 256, SMEM_CONV>>>(p_s, p_wp2, nullptr, p_hwc1);   // y2
    conv_tf32<9, 12><<<Bb * Hh, 256, SMEM_CONV>>>(p_s, p_wp3, nullptr, p_whc1);  // y3
    conv_tf32<1, 1><<<Bb * Hh, 256, SMEM_CONV>>>(p_s, p_wp1, nullptr, p_y);      // y1
    // depthwise branch: att -> g_whc2 (pre-rounded at write)
    dw_kernel<<<Bb * Cc, 256, HW * 4>>>(p_x1, w1, b1, w2, b2, w3, b3, w4, b4, w5, b5, w6, b6, p_whc2);
    // BN stats + fused bn-relu-sum (pre-rounded at write) -> g_s
    chan_stats3<<<3 * Cc, 256>>>(p_y, p_hwc1, p_whc1);
    bnrelu3<<<NELEM / 256, 256>>>(p_y, p_hwc1, p_whc1, gd1, bd1, gd2, bd2, gd3, bd3, p_s);
    // out2 = conv1x1(sum, w_out1) + x
    conv_tf32<1, 1><<<Bb * Hh, 256, SMEM_CONV>>>(p_s, p_wpo1, x, p_out2);
    // out1 = conv1x1(att, w_out2) -> g_x1
    conv_tf32<1, 1><<<Bb * Hh, 256, SMEM_CONV>>>(p_whc2, p_wpo2, nullptr, p_x1);

    // rearranges + norms
    rearrange_out1<<<BH * Hh, 256>>>(p_x1, p_hwc1, p_whc1, p_n1);
    whc_kernel<<<BH * Hh, 256>>>(p_out2, p_whc2);
    rownorm2<<<2 * BH * Ww, 256>>>(p_whc1, p_whc2, p_n2, p_n3);

    // attention
    qk_tf32<<<dim3(BH, 2), 256>>>(p_whc2, p_hwc1, p_n3, p_n1, p_A1);
    qk_tf32<<<dim3(BH, 2), 256>>>(p_whc1, p_whc2, p_n2, p_n3, p_A2);
    av_tf32<<<dim3(BH, 16), 256>>>(p_A1, p_hwc1, p_whc2, p_n3, p_s);   // out3
    av_tf32<<<dim3(BH, 16), 256>>>(p_A2, p_whc2, p_whc1, p_n2, p_y);   // out4

    // merge (pre-rounded) + final conv
    merge_kernel<<<BH * Hh, 256>>>(p_s, p_y, p_out2);
    conv_tf32<1, 1><<<Bb * Hh, 256, SMEM_CONV>>>(p_out2, p_wpo2, x, outp);
}